// round 2
// baseline (speedup 1.0000x reference)
#include <cuda_runtime.h>
#include <cuda_bf16.h>
#include <cuda_fp16.h>
#include <cstdint>
#include <cstddef>

// Problem constants
#define BATCH   4096
#define DIM     512
#define QSIZE   32768
#define NHARD   9830
#define NRAND   22938
#define INV_T   (1.0f/0.07f)

// -------- device scratch (static allocation; no cudaMalloc allowed) --------
__device__ __nv_bfloat16 g_eegn[BATCH * DIM];            // 4 MB  normalized eeg, bf16
__device__ __nv_bfloat16 g_qbf[QSIZE * DIM];             // 32 MB queue, bf16
__device__ __half        g_neg[(size_t)BATCH * QSIZE];   // 256 MB similarity matrix, fp16
__device__ float         g_pos[BATCH];
__device__ double        g_sums[2];                      // [0]=loss sum, [1]=correct sum

// ---------------------------------------------------------------------------
__global__ void k_zero() { g_sums[0] = 0.0; g_sums[1] = 0.0; }

// Normalize eeg (write bf16) and compute pos = <eeg_n, clip_n> per row.
__global__ __launch_bounds__(128) void k_norm(const float* __restrict__ eeg,
                                              const float* __restrict__ clip) {
    int b = blockIdx.x, t = threadIdx.x;
    float4 e = ((const float4*)(eeg  + (size_t)b * DIM))[t];
    float4 c = ((const float4*)(clip + (size_t)b * DIM))[t];
    float se = e.x*e.x + e.y*e.y + e.z*e.z + e.w*e.w;
    float sc = c.x*c.x + c.y*c.y + c.z*c.z + c.w*c.w;
    float sd = e.x*c.x + e.y*c.y + e.z*c.z + e.w*c.w;
    #pragma unroll
    for (int o = 16; o; o >>= 1) {
        se += __shfl_down_sync(0xFFFFFFFFu, se, o);
        sc += __shfl_down_sync(0xFFFFFFFFu, sc, o);
        sd += __shfl_down_sync(0xFFFFFFFFu, sd, o);
    }
    __shared__ float rs[3][4];
    __shared__ float sInvE;
    int w = t >> 5, l = t & 31;
    if (l == 0) { rs[0][w] = se; rs[1][w] = sc; rs[2][w] = sd; }
    __syncthreads();
    if (t == 0) {
        float SE = rs[0][0] + rs[0][1] + rs[0][2] + rs[0][3];
        float SC = rs[1][0] + rs[1][1] + rs[1][2] + rs[1][3];
        float SD = rs[2][0] + rs[2][1] + rs[2][2] + rs[2][3];
        float ie = 1.0f / fmaxf(sqrtf(SE), 1e-12f);
        float ic = 1.0f / fmaxf(sqrtf(SC), 1e-12f);
        sInvE = ie;
        g_pos[b] = SD * ie * ic;
    }
    __syncthreads();
    float ie = sInvE;
    __nv_bfloat16* dst = g_eegn + (size_t)b * DIM + t * 4;
    dst[0] = __float2bfloat16(e.x * ie);
    dst[1] = __float2bfloat16(e.y * ie);
    dst[2] = __float2bfloat16(e.z * ie);
    dst[3] = __float2bfloat16(e.w * ie);
}

// Convert queue fp32 -> bf16 (queue is pre-normalized by the reference setup).
__global__ __launch_bounds__(256) void k_convq(const float* __restrict__ q) {
    int i = blockIdx.x * 256 + threadIdx.x;      // float4 index, total QSIZE*DIM/4
    float4 v = ((const float4*)q)[i];
    __nv_bfloat162* d = (__nv_bfloat162*)g_qbf;
    d[2 * i]     = __floats2bfloat162_rn(v.x, v.y);
    d[2 * i + 1] = __floats2bfloat162_rn(v.z, v.w);
}

// ---------------------------------------------------------------------------
// bf16 GEMM: neg[m][n] = sum_k eegn[m][k] * qbf[n][k]   (both K-contiguous)
// mma.sync m16n8k16 row.col, cp.async double-buffered, CTA tile 128x128x32.
// ---------------------------------------------------------------------------
__device__ __forceinline__ uint32_t smem_u32(const void* p) {
    return (uint32_t)__cvta_generic_to_shared(p);
}
__device__ __forceinline__ void cp16(uint32_t s, const void* g) {
    asm volatile("cp.async.cg.shared.global [%0], [%1], 16;\n" :: "r"(s), "l"(g));
}
__device__ __forceinline__ void cp_commit() { asm volatile("cp.async.commit_group;\n"); }
template <int N> __device__ __forceinline__ void cp_wait() {
    asm volatile("cp.async.wait_group %0;\n" :: "n"(N));
}

#define LDSK 40   // 32 + 8 pad: 80B row stride, 16B aligned, conflict-free ldmatrix

__global__ __launch_bounds__(256) void k_gemm() {
    __shared__ __align__(16) __nv_bfloat16 As[2][128 * LDSK];
    __shared__ __align__(16) __nv_bfloat16 Bs[2][128 * LDSK];
    int tid = threadIdx.x;
    int bn = blockIdx.x, bm = blockIdx.y;
    const __nv_bfloat16* Abase = g_eegn + (size_t)bm * 128 * DIM;
    const __nv_bfloat16* Bbase = g_qbf  + (size_t)bn * 128 * DIM;

    auto load_stage = [&](int s, int kt) {
        #pragma unroll
        for (int h = 0; h < 2; ++h) {
            int c = tid + h * 256;          // 512 chunks of 16B per operand
            int row = c >> 2, kc = c & 3;
            cp16(smem_u32(&As[s][row * LDSK + kc * 8]),
                 Abase + (size_t)row * DIM + kt * 32 + kc * 8);
            cp16(smem_u32(&Bs[s][row * LDSK + kc * 8]),
                 Bbase + (size_t)row * DIM + kt * 32 + kc * 8);
        }
        cp_commit();
    };

    float acc[4][4][4];
    #pragma unroll
    for (int i = 0; i < 4; i++)
        #pragma unroll
        for (int j = 0; j < 4; j++)
            #pragma unroll
            for (int r = 0; r < 4; r++) acc[i][j][r] = 0.0f;

    int warp = tid >> 5, lane = tid & 31;
    int wm = warp & 1, wn = warp >> 1;      // warp grid 2(m) x 4(n), warp tile 64x32

    load_stage(0, 0);
    for (int kt = 0; kt < DIM / 32; ++kt) {
        int cur = kt & 1;
        if (kt < DIM / 32 - 1) { load_stage(cur ^ 1, kt + 1); cp_wait<1>(); }
        else                   { cp_wait<0>(); }
        __syncthreads();
        #pragma unroll
        for (int ks = 0; ks < 2; ++ks) {
            uint32_t a[4][4];
            #pragma unroll
            for (int mi = 0; mi < 4; mi++) {
                int r  = wm * 64 + mi * 16 + (lane & 15);
                int kk = ks * 16 + (lane >> 4) * 8;
                uint32_t addr = smem_u32(&As[cur][r * LDSK + kk]);
                asm volatile("ldmatrix.sync.aligned.m8n8.x4.shared.b16 {%0,%1,%2,%3}, [%4];\n"
                    : "=r"(a[mi][0]), "=r"(a[mi][1]), "=r"(a[mi][2]), "=r"(a[mi][3])
                    : "r"(addr));
            }
            uint32_t bb[4][2];
            #pragma unroll
            for (int ni = 0; ni < 4; ni++) {
                int r  = wn * 32 + ni * 8 + (lane & 7);
                int kk = ks * 16 + ((lane >> 3) & 1) * 8;
                uint32_t addr = smem_u32(&Bs[cur][r * LDSK + kk]);
                asm volatile("ldmatrix.sync.aligned.m8n8.x2.shared.b16 {%0,%1}, [%2];\n"
                    : "=r"(bb[ni][0]), "=r"(bb[ni][1]) : "r"(addr));
            }
            #pragma unroll
            for (int mi = 0; mi < 4; mi++)
                #pragma unroll
                for (int ni = 0; ni < 4; ni++)
                    asm volatile(
                        "mma.sync.aligned.m16n8k16.row.col.f32.bf16.bf16.f32 "
                        "{%0,%1,%2,%3}, {%4,%5,%6,%7}, {%8,%9}, {%0,%1,%2,%3};\n"
                        : "+f"(acc[mi][ni][0]), "+f"(acc[mi][ni][1]),
                          "+f"(acc[mi][ni][2]), "+f"(acc[mi][ni][3])
                        : "r"(a[mi][0]), "r"(a[mi][1]), "r"(a[mi][2]), "r"(a[mi][3]),
                          "r"(bb[ni][0]), "r"(bb[ni][1]));
        }
        __syncthreads();
    }

    // Epilogue: fp32 accum -> fp16 store
    #pragma unroll
    for (int mi = 0; mi < 4; mi++) {
        #pragma unroll
        for (int ni = 0; ni < 4; ni++) {
            int row = bm * 128 + wm * 64 + mi * 16 + (lane >> 2);
            int col = bn * 128 + wn * 32 + ni * 8 + (lane & 3) * 2;
            *(__half2*)&g_neg[(size_t)row * QSIZE + col] =
                __floats2half2_rn(acc[mi][ni][0], acc[mi][ni][1]);
            *(__half2*)&g_neg[(size_t)(row + 8) * QSIZE + col] =
                __floats2half2_rn(acc[mi][ni][2], acc[mi][ni][3]);
        }
    }
}

// ---------------------------------------------------------------------------
// Per-row: rowmax, 2-level histogram k-select, top-k exp-sum, gather exp-sum.
// One CTA (256 thr) per row; row cached in smem as fp16 (64KB) + 2048-bin hist.
// ---------------------------------------------------------------------------
__global__ __launch_bounds__(256) void k_select(const int* __restrict__ ridx) {
    extern __shared__ unsigned char dyn[];
    __half* srow = (__half*)dyn;                       // 65536 B
    int*    hist = (int*)(dyn + sizeof(__half) * QSIZE); // 8192 B
    __shared__ int   chunkSum[256];
    __shared__ int   s_bin, s_cnt;
    __shared__ float s_red[256];

    int b = blockIdx.x, tid = threadIdx.x;

    const uint4* src = (const uint4*)(g_neg + (size_t)b * QSIZE);
    uint4* dst4 = (uint4*)srow;
    for (int i = tid; i < QSIZE / 8; i += 256) dst4[i] = src[i];
    for (int i = tid; i < 2048; i += 256) hist[i] = 0;
    __syncthreads();

    // rowmax + level-1 histogram over [-1, 1], 2048 bins
    float lmax = -2.0f;
    for (int i = tid; i < QSIZE; i += 256) {
        float s = __half2float(srow[i]);
        lmax = fmaxf(lmax, s);
        int bin = (int)((s + 1.0f) * 1024.0f);
        bin = bin < 0 ? 0 : (bin > 2047 ? 2047 : bin);
        atomicAdd(&hist[bin], 1);
    }
    s_red[tid] = lmax; __syncthreads();
    #pragma unroll
    for (int st = 128; st; st >>= 1) {
        if (tid < st) s_red[tid] = fmaxf(s_red[tid], s_red[tid + st]);
        __syncthreads();
    }
    float rowmax = s_red[0];
    __syncthreads();

    // level-1 scan from the top: find bin1 with cntAbove < NHARD <= cntAbove+hist
    {
        int base = tid * 8, sum = 0;
        #pragma unroll
        for (int j = 0; j < 8; j++) sum += hist[base + j];
        chunkSum[tid] = sum; __syncthreads();
        int suf = 0;
        for (int t = tid + 1; t < 256; t++) suf += chunkSum[t];
        if (suf < NHARD && suf + chunkSum[tid] >= NHARD) {
            int c = suf;
            #pragma unroll
            for (int j = 7; j >= 0; j--) {
                int h = hist[base + j];
                if (c + h >= NHARD) { s_bin = base + j; s_cnt = c; break; }
                c += h;
            }
        }
        __syncthreads();
    }
    int bin1 = s_bin, need = NHARD - s_cnt;
    float lo = (float)bin1 * (1.0f / 1024.0f) - 1.0f;
    __syncthreads();
    for (int i = tid; i < 2048; i += 256) hist[i] = 0;
    __syncthreads();

    // sum exp over bins > bin1; sub-histogram the boundary bin
    float accH = 0.0f;
    for (int i = tid; i < QSIZE; i += 256) {
        float s = __half2float(srow[i]);
        int bin = (int)((s + 1.0f) * 1024.0f);
        bin = bin < 0 ? 0 : (bin > 2047 ? 2047 : bin);
        if (bin > bin1) accH += __expf(s * INV_T);
        else if (bin == bin1) {
            int sb = (int)((s - lo) * (1024.0f * 2048.0f));
            sb = sb < 0 ? 0 : (sb > 2047 ? 2047 : sb);
            atomicAdd(&hist[sb], 1);
        }
    }
    __syncthreads();

    // level-2 scan for `need`
    {
        int base = tid * 8, sum = 0;
        #pragma unroll
        for (int j = 0; j < 8; j++) sum += hist[base + j];
        chunkSum[tid] = sum; __syncthreads();
        int suf = 0;
        for (int t = tid + 1; t < 256; t++) suf += chunkSum[t];
        if (suf < need && suf + chunkSum[tid] >= need) {
            int c = suf;
            #pragma unroll
            for (int j = 7; j >= 0; j--) {
                int h = hist[base + j];
                if (c + h >= need) { s_bin = base + j; s_cnt = c; break; }
                c += h;
            }
        }
        __syncthreads();
    }
    int sb1 = s_bin, rem = need - s_cnt;

    // sum exp over boundary-bin values above sub-threshold
    for (int i = tid; i < QSIZE; i += 256) {
        float s = __half2float(srow[i]);
        int bin = (int)((s + 1.0f) * 1024.0f);
        bin = bin < 0 ? 0 : (bin > 2047 ? 2047 : bin);
        if (bin == bin1) {
            int sb = (int)((s - lo) * (1024.0f * 2048.0f));
            sb = sb < 0 ? 0 : (sb > 2047 ? 2047 : sb);
            if (sb > sb1) accH += __expf(s * INV_T);
        }
    }
    if (tid == 0) {   // residual values inside sub-bin sb1 (width 4.8e-7): midpoint approx
        float smid = lo + ((float)sb1 + 0.5f) * (1.0f / (1024.0f * 2048.0f));
        accH += (float)rem * __expf(smid * INV_T);
    }

    // random-negative gather from smem
    float accR = 0.0f;
    const int* ri = ridx + (size_t)b * NRAND;
    for (int i = tid; i < NRAND; i += 256)
        accR += __expf(__half2float(srow[ri[i]]) * INV_T);

    s_red[tid] = accH + accR; __syncthreads();
    #pragma unroll
    for (int st = 128; st; st >>= 1) {
        if (tid < st) s_red[tid] += s_red[tid + st];
        __syncthreads();
    }
    if (tid == 0) {
        float p = g_pos[b] * INV_T;
        float total = s_red[0] + __expf(p);
        float lossb = logf(total) - p;
        atomicAdd(&g_sums[0], (double)lossb);
        atomicAdd(&g_sums[1], (g_pos[b] >= rowmax) ? 1.0 : 0.0);
    }
}

__global__ void k_final(float* out, int n) {
    if (n >= 1) out[0] = (float)(g_sums[0] / (double)BATCH);
    if (n >= 2) out[1] = (float)(g_sums[1] / (double)BATCH);
}

// ---------------------------------------------------------------------------
extern "C" void kernel_launch(void* const* d_in, const int* in_sizes, int n_in,
                              void* d_out, int out_size) {
    const float* eeg   = (const float*)d_in[0];
    const float* clip  = (const float*)d_in[1];
    const float* queue = (const float*)d_in[2];
    const int*   ridx  = (const int*)d_in[3];
    float* out = (float*)d_out;

    // idempotent, capture-safe (not a stream op, not an allocation)
    cudaFuncSetAttribute(k_select, cudaFuncAttributeMaxDynamicSharedMemorySize,
                         QSIZE * 2 + 2048 * 4);

    k_zero<<<1, 1>>>();
    k_norm<<<BATCH, 128>>>(eeg, clip);
    k_convq<<<QSIZE * DIM / 4 / 256, 256>>>(queue);
    k_gemm<<<dim3(QSIZE / 128, BATCH / 128), 256>>>();
    k_select<<<BATCH, 256, QSIZE * 2 + 2048 * 4>>>(ridx);
    k_final<<<1, 1>>>(out, out_size);
}

// round 4
// speedup vs baseline: 1.1499x; 1.1499x over previous
#include <cuda_runtime.h>
#include <cuda_bf16.h>
#include <cuda_fp16.h>
#include <cstdint>
#include <cstddef>

// Problem constants
#define BATCH   4096
#define DIM     512
#define QSIZE   32768
#define NHARD   9830
#define NRAND   22938
#define INV_T   (1.0f/0.07f)

// -------- device scratch (static allocation; no cudaMalloc allowed) --------
__device__ __nv_bfloat16 g_eegn[BATCH * DIM];            // 4 MB
__device__ __nv_bfloat16 g_qbf[QSIZE * DIM];             // 32 MB
__device__ __half        g_neg[(size_t)BATCH * QSIZE];   // 256 MB
__device__ float         g_pos[BATCH];
__device__ double        g_sums[2];

// ---------------------------------------------------------------------------
__global__ void k_zero() { g_sums[0] = 0.0; g_sums[1] = 0.0; }

__global__ __launch_bounds__(128) void k_norm(const float* __restrict__ eeg,
                                              const float* __restrict__ clip) {
    int b = blockIdx.x, t = threadIdx.x;
    float4 e = ((const float4*)(eeg  + (size_t)b * DIM))[t];
    float4 c = ((const float4*)(clip + (size_t)b * DIM))[t];
    float se = e.x*e.x + e.y*e.y + e.z*e.z + e.w*e.w;
    float sc = c.x*c.x + c.y*c.y + c.z*c.z + c.w*c.w;
    float sd = e.x*c.x + e.y*c.y + e.z*c.z + e.w*c.w;
    #pragma unroll
    for (int o = 16; o; o >>= 1) {
        se += __shfl_down_sync(0xFFFFFFFFu, se, o);
        sc += __shfl_down_sync(0xFFFFFFFFu, sc, o);
        sd += __shfl_down_sync(0xFFFFFFFFu, sd, o);
    }
    __shared__ float rs[3][4];
    __shared__ float sInvE;
    int w = t >> 5, l = t & 31;
    if (l == 0) { rs[0][w] = se; rs[1][w] = sc; rs[2][w] = sd; }
    __syncthreads();
    if (t == 0) {
        float SE = rs[0][0] + rs[0][1] + rs[0][2] + rs[0][3];
        float SC = rs[1][0] + rs[1][1] + rs[1][2] + rs[1][3];
        float SD = rs[2][0] + rs[2][1] + rs[2][2] + rs[2][3];
        float ie = 1.0f / fmaxf(sqrtf(SE), 1e-12f);
        float ic = 1.0f / fmaxf(sqrtf(SC), 1e-12f);
        sInvE = ie;
        g_pos[b] = SD * ie * ic;
    }
    __syncthreads();
    float ie = sInvE;
    __nv_bfloat16* dst = g_eegn + (size_t)b * DIM + t * 4;
    dst[0] = __float2bfloat16(e.x * ie);
    dst[1] = __float2bfloat16(e.y * ie);
    dst[2] = __float2bfloat16(e.z * ie);
    dst[3] = __float2bfloat16(e.w * ie);
}

__global__ __launch_bounds__(256) void k_convq(const float* __restrict__ q) {
    int i = blockIdx.x * 256 + threadIdx.x;
    float4 v = ((const float4*)q)[i];
    __nv_bfloat162* d = (__nv_bfloat162*)g_qbf;
    d[2 * i]     = __floats2bfloat162_rn(v.x, v.y);
    d[2 * i + 1] = __floats2bfloat162_rn(v.z, v.w);
}

// ---------------------------------------------------------------------------
// mma.sync GEMM: neg[m][n] = sum_k eegn[m][k] * qbf[n][k]
// CTA tile 128x256, warp tile 64x64 (2x4 warp grid), K=32/stage, 6 stages.
// ---------------------------------------------------------------------------
__device__ __forceinline__ uint32_t smem_u32(const void* p) {
    return (uint32_t)__cvta_generic_to_shared(p);
}
__device__ __forceinline__ void cp16(uint32_t s, const void* g) {
    asm volatile("cp.async.cg.shared.global [%0], [%1], 16;\n" :: "r"(s), "l"(g));
}
__device__ __forceinline__ void cp_commit() { asm volatile("cp.async.commit_group;\n"); }
template <int N> __device__ __forceinline__ void cp_wait() {
    asm volatile("cp.async.wait_group %0;\n" :: "n"(N));
}

#define LDSK 40                        // 32 + 8 pad elems: 80B rows, conflict-free
#define STAGES 6
#define KTILES 16                      // DIM / 32
#define A_STAGE_B (128 * LDSK * 2)     // 10240 B
#define B_STAGE_B (256 * LDSK * 2)     // 20480 B
#define STAGE_B   (A_STAGE_B + B_STAGE_B)
#define GEMM_SMEM (STAGES * STAGE_B)   // 184320 B

__global__ __launch_bounds__(256) void k_gemm() {
    extern __shared__ __align__(16) unsigned char smraw[];
    uint32_t sbase = smem_u32(smraw);
    int tid = threadIdx.x, warp = tid >> 5, lane = tid & 31;
    int bn = blockIdx.x, bm = blockIdx.y;
    int wm = warp & 1, wn = warp >> 1;   // 2(m) x 4(n); warp tile 64x64

    const __nv_bfloat16* Abase = g_eegn + (size_t)bm * 128 * DIM;
    const __nv_bfloat16* Bbase = g_qbf  + (size_t)bn * 256 * DIM;

    auto load_stage = [&](int s, int kt) {
        uint32_t sa = sbase + s * STAGE_B;
        uint32_t sb = sa + A_STAGE_B;
        #pragma unroll
        for (int i = 0; i < 6; ++i) {               // 1536 16B chunks / 256 thr
            int c = tid + i * 256;
            uint32_t dst; const __nv_bfloat16* g; int row, col;
            if (c < 512) { row = c >> 2; col = c & 3; dst = sa;
                           g = Abase + (size_t)row * DIM + kt * 32 + col * 8; }
            else { int cb = c - 512; row = cb >> 2; col = cb & 3; dst = sb;
                   g = Bbase + (size_t)row * DIM + kt * 32 + col * 8; }
            cp16(dst + (uint32_t)(row * (LDSK * 2) + col * 16), g);
        }
    };

    float acc[4][8][4];
    #pragma unroll
    for (int i = 0; i < 4; i++)
        #pragma unroll
        for (int j = 0; j < 8; j++)
            #pragma unroll
            for (int r = 0; r < 4; r++) acc[i][j][r] = 0.0f;

    #pragma unroll
    for (int s = 0; s < STAGES - 1; ++s) { load_stage(s, s); cp_commit(); }

    for (int kt = 0; kt < KTILES; ++kt) {
        cp_wait<STAGES - 2>();
        __syncthreads();
        if (kt + STAGES - 1 < KTILES) load_stage((kt + STAGES - 1) % STAGES, kt + STAGES - 1);
        cp_commit();                   // empty commit near the tail keeps accounting exact

        uint32_t sa = sbase + (kt % STAGES) * STAGE_B;
        uint32_t sb = sa + A_STAGE_B;
        #pragma unroll
        for (int ks = 0; ks < 2; ++ks) {
            uint32_t a[4][4];
            #pragma unroll
            for (int mi = 0; mi < 4; mi++) {
                int r  = wm * 64 + mi * 16 + (lane & 15);
                int kk = ks * 16 + (lane >> 4) * 8;
                uint32_t addr = sa + (uint32_t)(r * (LDSK * 2) + kk * 2);
                asm volatile("ldmatrix.sync.aligned.m8n8.x4.shared.b16 {%0,%1,%2,%3}, [%4];\n"
                    : "=r"(a[mi][0]), "=r"(a[mi][1]), "=r"(a[mi][2]), "=r"(a[mi][3])
                    : "r"(addr));
            }
            uint32_t bb[8][2];
            #pragma unroll
            for (int ni = 0; ni < 8; ni++) {
                int r  = wn * 64 + ni * 8 + (lane & 7);
                int kk = ks * 16 + ((lane >> 3) & 1) * 8;
                uint32_t addr = sb + (uint32_t)(r * (LDSK * 2) + kk * 2);
                asm volatile("ldmatrix.sync.aligned.m8n8.x2.shared.b16 {%0,%1}, [%2];\n"
                    : "=r"(bb[ni][0]), "=r"(bb[ni][1]) : "r"(addr));
            }
            #pragma unroll
            for (int mi = 0; mi < 4; mi++)
                #pragma unroll
                for (int ni = 0; ni < 8; ni++)
                    asm volatile(
                        "mma.sync.aligned.m16n8k16.row.col.f32.bf16.bf16.f32 "
                        "{%0,%1,%2,%3}, {%4,%5,%6,%7}, {%8,%9}, {%0,%1,%2,%3};\n"
                        : "+f"(acc[mi][ni][0]), "+f"(acc[mi][ni][1]),
                          "+f"(acc[mi][ni][2]), "+f"(acc[mi][ni][3])
                        : "r"(a[mi][0]), "r"(a[mi][1]), "r"(a[mi][2]), "r"(a[mi][3]),
                          "r"(bb[ni][0]), "r"(bb[ni][1]));
        }
    }

    // Epilogue: fp32 -> fp16 store
    #pragma unroll
    for (int mi = 0; mi < 4; mi++) {
        #pragma unroll
        for (int ni = 0; ni < 8; ni++) {
            int row = bm * 128 + wm * 64 + mi * 16 + (lane >> 2);
            int col = bn * 256 + wn * 64 + ni * 8 + (lane & 3) * 2;
            *(__half2*)&g_neg[(size_t)row * QSIZE + col] =
                __floats2half2_rn(acc[mi][ni][0], acc[mi][ni][1]);
            *(__half2*)&g_neg[(size_t)(row + 8) * QSIZE + col] =
                __floats2half2_rn(acc[mi][ni][2], acc[mi][ni][3]);
        }
    }
}

// ---------------------------------------------------------------------------
// k_select: 512 threads/CTA; 2 full passes + compact level-2 + gather.
// ---------------------------------------------------------------------------
#define SEL_T 512
#define CBUF_CAP 8192
#define SEL_SMEM (QSIZE*2 + 2048*4 + CBUF_CAP*2)

__device__ __forceinline__ void find_bin(int* hist, int target, int* scs,
                                         int* out_bin, int* out_above, int tid) {
    int base = tid * 4;
    int c = hist[base] + hist[base+1] + hist[base+2] + hist[base+3];
    scs[tid] = c;
    __syncthreads();
    #pragma unroll
    for (int d = 1; d < SEL_T; d <<= 1) {
        int v = (tid + d < SEL_T) ? scs[tid + d] : 0;
        __syncthreads();
        scs[tid] += v;
        __syncthreads();
    }
    int Sincl = scs[tid];
    int Sexcl = (tid + 1 < SEL_T) ? scs[tid + 1] : 0;
    if (Sexcl < target && Sincl >= target) {
        int ca = Sexcl;
        #pragma unroll
        for (int j = 3; j >= 0; --j) {
            int h = hist[base + j];
            if (ca + h >= target) { *out_bin = base + j; *out_above = ca; break; }
            ca += h;
        }
    }
}

__global__ __launch_bounds__(SEL_T) void k_select(const int* __restrict__ ridx) {
    extern __shared__ unsigned char dyn2[];
    __half* srow = (__half*)dyn2;                          // 65536 B
    int*    hist = (int*)(dyn2 + QSIZE*2);                 // 8192 B
    __half* cbuf = (__half*)(dyn2 + QSIZE*2 + 2048*4);     // 16384 B
    __shared__ int   scs[SEL_T];
    __shared__ float wred[SEL_T/32];
    __shared__ int   s_bin, s_above, s_nc;
    __shared__ float s_max;

    int b = blockIdx.x, tid = threadIdx.x;

    for (int i = tid; i < 2048; i += SEL_T) hist[i] = 0;
    if (tid == 0) s_nc = 0;
    __syncthreads();

    // pass 1: load row -> smem, rowmax, level-1 histogram (2048 bins over [-1,1])
    const uint4* src = (const uint4*)(g_neg + (size_t)b * QSIZE);
    uint4* drow = (uint4*)srow;
    float lmax = -2.0f;
    for (int i = tid; i < QSIZE / 8; i += SEL_T) {
        uint4 v = src[i]; drow[i] = v;
        uint32_t ws[4] = {v.x, v.y, v.z, v.w};
        #pragma unroll
        for (int q = 0; q < 4; ++q) {
            float2 f = __half22float2(*(__half2*)&ws[q]);
            lmax = fmaxf(lmax, fmaxf(f.x, f.y));
            int b0 = (int)((f.x + 1.0f) * 1024.0f); b0 = min(max(b0, 0), 2047);
            int b1 = (int)((f.y + 1.0f) * 1024.0f); b1 = min(max(b1, 0), 2047);
            atomicAdd(&hist[b0], 1);
            atomicAdd(&hist[b1], 1);
        }
    }
    #pragma unroll
    for (int o = 16; o; o >>= 1) lmax = fmaxf(lmax, __shfl_xor_sync(0xFFFFFFFFu, lmax, o));
    if ((tid & 31) == 0) wred[tid >> 5] = lmax;
    __syncthreads();
    if (tid == 0) {
        float m = -2.0f;
        for (int w = 0; w < SEL_T/32; ++w) m = fmaxf(m, wred[w]);
        s_max = m;
    }
    __syncthreads();
    float rowmax = s_max;

    find_bin(hist, NHARD, scs, &s_bin, &s_above, tid);
    __syncthreads();
    int bin1 = s_bin, need = NHARD - s_above;
    float lo = (float)bin1 * (1.0f / 1024.0f) - 1.0f;
    __syncthreads();

    // pass 2: exp-sum above bin1, compact boundary bin
    float acc = 0.0f;
    for (int i = tid; i < QSIZE; i += SEL_T) {
        float s = __half2float(srow[i]);
        int bb = (int)((s + 1.0f) * 1024.0f); bb = min(max(bb, 0), 2047);
        if (bb > bin1) acc += __expf(s * INV_T);
        else if (bb == bin1) {
            int p = atomicAdd(&s_nc, 1);
            if (p < CBUF_CAP) cbuf[p] = srow[i];
        }
    }
    __syncthreads();
    int nc = min(s_nc, CBUF_CAP);
    for (int i = tid; i < 2048; i += SEL_T) hist[i] = 0;
    __syncthreads();
    for (int i = tid; i < nc; i += SEL_T) {
        float s = __half2float(cbuf[i]);
        int sb = (int)((s - lo) * (1024.0f * 2048.0f)); sb = min(max(sb, 0), 2047);
        atomicAdd(&hist[sb], 1);
    }
    __syncthreads();
    find_bin(hist, need, scs, &s_bin, &s_above, tid);
    __syncthreads();
    int sb1 = s_bin, above2 = s_above;
    for (int i = tid; i < nc; i += SEL_T) {
        float s = __half2float(cbuf[i]);
        int sb = (int)((s - lo) * (1024.0f * 2048.0f)); sb = min(max(sb, 0), 2047);
        if (sb > sb1) acc += __expf(s * INV_T);
    }
    if (tid == 0) {
        int rem = need - above2;
        float smid = lo + ((float)sb1 + 0.5f) * (1.0f / (1024.0f * 2048.0f));
        acc += (float)rem * __expf(smid * INV_T);
    }

    // random-negative gather
    const int* ri = ridx + (size_t)b * NRAND;
    for (int i = tid; i < NRAND; i += SEL_T)
        acc += __expf(__half2float(srow[__ldg(ri + i)]) * INV_T);

    #pragma unroll
    for (int o = 16; o; o >>= 1) acc += __shfl_xor_sync(0xFFFFFFFFu, acc, o);
    if ((tid & 31) == 0) wred[tid >> 5] = acc;
    __syncthreads();
    if (tid == 0) {
        float tot = 0.0f;
        for (int w = 0; w < SEL_T/32; ++w) tot += wred[w];
        float p = g_pos[b] * INV_T;
        tot += __expf(p);
        atomicAdd(&g_sums[0], (double)(logf(tot) - p));
        atomicAdd(&g_sums[1], (g_pos[b] >= rowmax) ? 1.0 : 0.0);
    }
}

__global__ void k_final(float* out, int n) {
    if (n >= 1) out[0] = (float)(g_sums[0] / (double)BATCH);
    if (n >= 2) out[1] = (float)(g_sums[1] / (double)BATCH);
}

// ---------------------------------------------------------------------------
extern "C" void kernel_launch(void* const* d_in, const int* in_sizes, int n_in,
                              void* d_out, int out_size) {
    const float* eeg   = (const float*)d_in[0];
    const float* clip  = (const float*)d_in[1];
    const float* queue = (const float*)d_in[2];
    const int*   ridx  = (const int*)d_in[3];
    float* out = (float*)d_out;

    cudaFuncSetAttribute(k_gemm,   cudaFuncAttributeMaxDynamicSharedMemorySize, GEMM_SMEM);
    cudaFuncSetAttribute(k_select, cudaFuncAttributeMaxDynamicSharedMemorySize, SEL_SMEM);

    k_zero<<<1, 1>>>();
    k_norm<<<BATCH, 128>>>(eeg, clip);
    k_convq<<<QSIZE * DIM / 4 / 256, 256>>>(queue);
    k_gemm<<<dim3(QSIZE / 256, BATCH / 128), 256, GEMM_SMEM>>>();
    k_select<<<BATCH, SEL_T, SEL_SMEM>>>(ridx);
    k_final<<<1, 1>>>(out, out_size);
}

// round 5
// speedup vs baseline: 1.2928x; 1.1243x over previous
#include <cuda_runtime.h>
#include <cuda_bf16.h>
#include <cuda_fp16.h>
#include <cstdint>
#include <cstddef>

// Problem constants
#define BATCH   4096
#define DIM     512
#define QSIZE   32768
#define NHARD   9830
#define NRAND   22938
#define INV_T   (1.0f/0.07f)
#define KEXP    (INV_T * 1.44269504f)   // log2(e)/T

// -------- device scratch (static allocation; no cudaMalloc allowed) --------
__device__ __nv_bfloat16 g_eegn[BATCH * DIM];            // 4 MB
__device__ __nv_bfloat16 g_qbf[QSIZE * DIM];             // 32 MB
__device__ __half        g_neg[(size_t)BATCH * QSIZE];   // 256 MB
__device__ float         g_pos[BATCH];
__device__ double        g_sums[2];

// ---------------------------------------------------------------------------
__global__ void k_zero() { g_sums[0] = 0.0; g_sums[1] = 0.0; }

__global__ __launch_bounds__(128) void k_norm(const float* __restrict__ eeg,
                                              const float* __restrict__ clip) {
    int b = blockIdx.x, t = threadIdx.x;
    float4 e = ((const float4*)(eeg  + (size_t)b * DIM))[t];
    float4 c = ((const float4*)(clip + (size_t)b * DIM))[t];
    float se = e.x*e.x + e.y*e.y + e.z*e.z + e.w*e.w;
    float sc = c.x*c.x + c.y*c.y + c.z*c.z + c.w*c.w;
    float sd = e.x*c.x + e.y*c.y + e.z*c.z + e.w*c.w;
    #pragma unroll
    for (int o = 16; o; o >>= 1) {
        se += __shfl_down_sync(0xFFFFFFFFu, se, o);
        sc += __shfl_down_sync(0xFFFFFFFFu, sc, o);
        sd += __shfl_down_sync(0xFFFFFFFFu, sd, o);
    }
    __shared__ float rs[3][4];
    __shared__ float sInvE;
    int w = t >> 5, l = t & 31;
    if (l == 0) { rs[0][w] = se; rs[1][w] = sc; rs[2][w] = sd; }
    __syncthreads();
    if (t == 0) {
        float SE = rs[0][0] + rs[0][1] + rs[0][2] + rs[0][3];
        float SC = rs[1][0] + rs[1][1] + rs[1][2] + rs[1][3];
        float SD = rs[2][0] + rs[2][1] + rs[2][2] + rs[2][3];
        float ie = 1.0f / fmaxf(sqrtf(SE), 1e-12f);
        float ic = 1.0f / fmaxf(sqrtf(SC), 1e-12f);
        sInvE = ie;
        g_pos[b] = SD * ie * ic;
    }
    __syncthreads();
    float ie = sInvE;
    __nv_bfloat16* dst = g_eegn + (size_t)b * DIM + t * 4;
    dst[0] = __float2bfloat16(e.x * ie);
    dst[1] = __float2bfloat16(e.y * ie);
    dst[2] = __float2bfloat16(e.z * ie);
    dst[3] = __float2bfloat16(e.w * ie);
}

__global__ __launch_bounds__(256) void k_convq(const float* __restrict__ q) {
    int i = blockIdx.x * 256 + threadIdx.x;
    float4 v = ((const float4*)q)[i];
    __nv_bfloat162* d = (__nv_bfloat162*)g_qbf;
    d[2 * i]     = __floats2bfloat162_rn(v.x, v.y);
    d[2 * i + 1] = __floats2bfloat162_rn(v.z, v.w);
}

// ---------------------------------------------------------------------------
// mma.sync GEMM, CTA 128x256, warp 64x64, 6-stage cp.async, reg-pipelined.
// ---------------------------------------------------------------------------
__device__ __forceinline__ uint32_t smem_u32(const void* p) {
    return (uint32_t)__cvta_generic_to_shared(p);
}
__device__ __forceinline__ void cp16(uint32_t s, const void* g) {
    asm volatile("cp.async.cg.shared.global [%0], [%1], 16;\n" :: "r"(s), "l"(g));
}
__device__ __forceinline__ void cp_commit() { asm volatile("cp.async.commit_group;\n"); }
template <int N> __device__ __forceinline__ void cp_wait() {
    asm volatile("cp.async.wait_group %0;\n" :: "n"(N));
}

#define LDSK 40                        // 32 + 8 pad elems: 80B rows
#define STAGES 6
#define KTILES 16                      // DIM / 32
#define A_STAGE_B (128 * LDSK * 2)     // 10240 B
#define B_STAGE_B (256 * LDSK * 2)     // 20480 B
#define STAGE_B   (A_STAGE_B + B_STAGE_B)
#define GEMM_SMEM (STAGES * STAGE_B)   // 184320 B

__global__ __launch_bounds__(256, 1) void k_gemm() {
    extern __shared__ __align__(16) unsigned char smraw[];
    uint32_t sbase = smem_u32(smraw);
    int tid = threadIdx.x, warp = tid >> 5, lane = tid & 31;
    int bn = blockIdx.x, bm = blockIdx.y;
    int wm = warp & 1, wn = warp >> 1;   // 2(m) x 4(n); warp tile 64x64

    const __nv_bfloat16* Abase = g_eegn + (size_t)bm * 128 * DIM;
    const __nv_bfloat16* Bbase = g_qbf  + (size_t)bn * 256 * DIM;

    auto load_stage = [&](int s, int kt) {
        uint32_t sa = sbase + s * STAGE_B;
        uint32_t sb = sa + A_STAGE_B;
        #pragma unroll
        for (int i = 0; i < 6; ++i) {               // 1536 16B chunks / 256 thr
            int c = tid + i * 256;
            uint32_t dst; const __nv_bfloat16* g; int row, col;
            if (c < 512) { row = c >> 2; col = c & 3; dst = sa;
                           g = Abase + (size_t)row * DIM + kt * 32 + col * 8; }
            else { int cb = c - 512; row = cb >> 2; col = cb & 3; dst = sb;
                   g = Bbase + (size_t)row * DIM + kt * 32 + col * 8; }
            cp16(dst + (uint32_t)(row * (LDSK * 2) + col * 16), g);
        }
    };

    float acc[4][8][4];
    #pragma unroll
    for (int i = 0; i < 4; i++)
        #pragma unroll
        for (int j = 0; j < 8; j++)
            #pragma unroll
            for (int r = 0; r < 4; r++) acc[i][j][r] = 0.0f;

    uint32_t fa[2][4][4];   // [buf][mi][reg]
    uint32_t fb[2][4][4];   // [buf][ni-pair][reg]

    // A: x4 over 16 rows x 16 k;  B: x4 over 16 rows (two n8 tiles) x 16 k
    int aRow = wm * 64 + (lane & 15);
    int aK0  = (lane >> 4) * 8;
    int bRow = wn * 64 + (lane & 7) + ((lane & 16) >> 1);
    int bK0  = ((lane >> 3) & 1) * 8;

    auto lds_frags = [&](int buf, uint32_t sa, uint32_t sb, int ks) {
        #pragma unroll
        for (int mi = 0; mi < 4; mi++) {
            uint32_t addr = sa + (uint32_t)((aRow + mi * 16) * (LDSK * 2)
                                            + (ks * 16 + aK0) * 2);
            asm volatile("ldmatrix.sync.aligned.m8n8.x4.shared.b16 {%0,%1,%2,%3}, [%4];\n"
                : "=r"(fa[buf][mi][0]), "=r"(fa[buf][mi][1]),
                  "=r"(fa[buf][mi][2]), "=r"(fa[buf][mi][3]) : "r"(addr));
        }
        #pragma unroll
        for (int np = 0; np < 4; np++) {
            uint32_t addr = sb + (uint32_t)((bRow + np * 16) * (LDSK * 2)
                                            + (ks * 16 + bK0) * 2);
            asm volatile("ldmatrix.sync.aligned.m8n8.x4.shared.b16 {%0,%1,%2,%3}, [%4];\n"
                : "=r"(fb[buf][np][0]), "=r"(fb[buf][np][1]),
                  "=r"(fb[buf][np][2]), "=r"(fb[buf][np][3]) : "r"(addr));
        }
    };

    auto do_hmma = [&](int buf) {
        #pragma unroll
        for (int mi = 0; mi < 4; mi++)
            #pragma unroll
            for (int ni = 0; ni < 8; ni++) {
                uint32_t b0 = fb[buf][ni >> 1][(ni & 1) * 2 + 0];
                uint32_t b1 = fb[buf][ni >> 1][(ni & 1) * 2 + 1];
                asm volatile(
                    "mma.sync.aligned.m16n8k16.row.col.f32.bf16.bf16.f32 "
                    "{%0,%1,%2,%3}, {%4,%5,%6,%7}, {%8,%9}, {%0,%1,%2,%3};\n"
                    : "+f"(acc[mi][ni][0]), "+f"(acc[mi][ni][1]),
                      "+f"(acc[mi][ni][2]), "+f"(acc[mi][ni][3])
                    : "r"(fa[buf][mi][0]), "r"(fa[buf][mi][1]),
                      "r"(fa[buf][mi][2]), "r"(fa[buf][mi][3]),
                      "r"(b0), "r"(b1));
            }
    };

    #pragma unroll
    for (int s = 0; s < STAGES - 1; ++s) { load_stage(s, s); cp_commit(); }

    for (int kt = 0; kt < KTILES; ++kt) {
        cp_wait<3>();                    // guarantees stages kt AND kt+1 landed
        __syncthreads();                 // publish to all warps
        if (kt + STAGES - 1 < KTILES) load_stage((kt + STAGES - 1) % STAGES, kt + STAGES - 1);
        cp_commit();

        uint32_t sa = sbase + (kt % STAGES) * STAGE_B;
        uint32_t sb = sa + A_STAGE_B;
        if (kt == 0) lds_frags(0, sa, sb, 0);
        lds_frags(1, sa, sb, 1);         // prefetch ks=1 under HMMA(ks=0)
        do_hmma(0);
        if (kt + 1 < KTILES) {           // prefetch next kt ks=0 under HMMA(ks=1)
            uint32_t sa2 = sbase + ((kt + 1) % STAGES) * STAGE_B;
            lds_frags(0, sa2, sa2 + A_STAGE_B, 0);
        }
        do_hmma(1);
    }

    // Epilogue: fp32 -> fp16 store
    #pragma unroll
    for (int mi = 0; mi < 4; mi++) {
        #pragma unroll
        for (int ni = 0; ni < 8; ni++) {
            int row = bm * 128 + wm * 64 + mi * 16 + (lane >> 2);
            int col = bn * 256 + wn * 64 + ni * 8 + (lane & 3) * 2;
            *(__half2*)&g_neg[(size_t)row * QSIZE + col] =
                __floats2half2_rn(acc[mi][ni][0], acc[mi][ni][1]);
            *(__half2*)&g_neg[(size_t)(row + 8) * QSIZE + col] =
                __floats2half2_rn(acc[mi][ni][2], acc[mi][ni][3]);
        }
    }
}

// ---------------------------------------------------------------------------
// k_select: pass1 (load+max+hist), fused pass2 (f16x2 exp + exp-table), gather.
// All exp sums in scaled domain e^((s-rowmax)/T).
// ---------------------------------------------------------------------------
#define SEL_T 512
#define CBUF_CAP 8192
#define SEL_SMEM (QSIZE*2 + 2048*4 + CBUF_CAP*2)

__device__ __forceinline__ uint32_t h2ex2(uint32_t x) {
    uint32_t r;
    asm("ex2.approx.f16x2 %0, %1;" : "=r"(r) : "r"(x));
    return r;
}

__device__ __forceinline__ void find_bin(int* hist, int target, int* scs,
                                         int* out_bin, int* out_above, int tid) {
    int base = tid * 4;
    int c = hist[base] + hist[base+1] + hist[base+2] + hist[base+3];
    scs[tid] = c;
    __syncthreads();
    #pragma unroll
    for (int d = 1; d < SEL_T; d <<= 1) {
        int v = (tid + d < SEL_T) ? scs[tid + d] : 0;
        __syncthreads();
        scs[tid] += v;
        __syncthreads();
    }
    int Sincl = scs[tid];
    int Sexcl = (tid + 1 < SEL_T) ? scs[tid + 1] : 0;
    if (Sexcl < target && Sincl >= target) {
        int ca = Sexcl;
        #pragma unroll
        for (int j = 3; j >= 0; --j) {
            int h = hist[base + j];
            if (ca + h >= target) { *out_bin = base + j; *out_above = ca; break; }
            ca += h;
        }
    }
}

__global__ __launch_bounds__(SEL_T) void k_select(const int* __restrict__ ridx) {
    extern __shared__ unsigned char dyn2[];
    __half*  srow  = (__half*)dyn2;                         // 65536 B
    __half2* srow2 = (__half2*)dyn2;
    int*     hist  = (int*)(dyn2 + QSIZE*2);                // 8192 B
    __half*  cbuf  = (__half*)(dyn2 + QSIZE*2 + 2048*4);    // 16384 B
    __shared__ int   scs[SEL_T];
    __shared__ float wred[SEL_T/32];
    __shared__ int   s_bin, s_above, s_nc;
    __shared__ float s_max;

    int b = blockIdx.x, tid = threadIdx.x;

    for (int i = tid; i < 2048; i += SEL_T) hist[i] = 0;
    if (tid == 0) s_nc = 0;
    __syncthreads();

    // ---- pass 1: load row, rowmax (f16 pairwise), level-1 histogram
    const uint4* src = (const uint4*)(g_neg + (size_t)b * QSIZE);
    uint4* drow = (uint4*)srow;
    __half2 hm = __floats2half2_rn(-2.0f, -2.0f);
    for (int i = tid; i < QSIZE / 8; i += SEL_T) {
        uint4 v = src[i]; drow[i] = v;
        uint32_t ws[4] = {v.x, v.y, v.z, v.w};
        #pragma unroll
        for (int q = 0; q < 4; ++q) {
            __half2 h2 = *(__half2*)&ws[q];
            hm = __hmax2(hm, h2);
            float2 f = __half22float2(h2);
            int b0 = (int)((f.x + 1.0f) * 1024.0f); b0 = min(max(b0, 0), 2047);
            int b1 = (int)((f.y + 1.0f) * 1024.0f); b1 = min(max(b1, 0), 2047);
            atomicAdd(&hist[b0], 1);
            atomicAdd(&hist[b1], 1);
        }
    }
    float lmax = fmaxf(__low2float(hm), __high2float(hm));
    #pragma unroll
    for (int o = 16; o; o >>= 1) lmax = fmaxf(lmax, __shfl_xor_sync(0xFFFFFFFFu, lmax, o));
    if ((tid & 31) == 0) wred[tid >> 5] = lmax;
    __syncthreads();
    if (tid == 0) {
        float m = -2.0f;
        for (int w = 0; w < SEL_T/32; ++w) m = fmaxf(m, wred[w]);
        s_max = m;
    }
    __syncthreads();
    float rm = s_max;

    find_bin(hist, NHARD, scs, &s_bin, &s_above, tid);
    __syncthreads();
    int bin1 = s_bin, need = NHARD - s_above;
    float lo = (float)bin1 * (1.0f / 1024.0f) - 1.0f;
    __syncthreads();

    // ---- pass 2 (fused): masked scaled-exp sum, boundary compaction,
    //      overwrite srow with e^((s-rm)/T) as the gather table.
    float accx = 0.0f, accy = 0.0f;
    for (int i = tid; i < QSIZE / 2; i += SEL_T) {
        __half2 v2 = srow2[i];
        float2 f = __half22float2(v2);
        int b0 = (int)((f.x + 1.0f) * 1024.0f); b0 = min(max(b0, 0), 2047);
        int b1 = (int)((f.y + 1.0f) * 1024.0f); b1 = min(max(b1, 0), 2047);
        if (b0 == bin1) { int p = atomicAdd(&s_nc, 1); if (p < CBUF_CAP) cbuf[p] = __low2half(v2); }
        if (b1 == bin1) { int p = atomicAdd(&s_nc, 1); if (p < CBUF_CAP) cbuf[p] = __high2half(v2); }
        __half2 xh = __floats2half2_rn((f.x - rm) * KEXP, (f.y - rm) * KEXP);
        uint32_t eu = h2ex2(*(uint32_t*)&xh);
        __half2 e2 = *(__half2*)&eu;
        float2 ef = __half22float2(e2);
        if (b0 > bin1) accx += ef.x;
        if (b1 > bin1) accy += ef.y;
        srow2[i] = e2;
    }
    float acc = accx + accy;
    __syncthreads();

    // ---- level 2 on the compacted boundary bin (exact to fp16 granularity)
    int nc = min(s_nc, CBUF_CAP);
    for (int i = tid; i < 2048; i += SEL_T) hist[i] = 0;
    __syncthreads();
    for (int i = tid; i < nc; i += SEL_T) {
        float s = __half2float(cbuf[i]);
        int sb = (int)((s - lo) * (1024.0f * 2048.0f)); sb = min(max(sb, 0), 2047);
        atomicAdd(&hist[sb], 1);
    }
    __syncthreads();
    find_bin(hist, need, scs, &s_bin, &s_above, tid);
    __syncthreads();
    int sb1 = s_bin, above2 = s_above;
    for (int i = tid; i < nc; i += SEL_T) {
        float s = __half2float(cbuf[i]);
        int sb = (int)((s - lo) * (1024.0f * 2048.0f)); sb = min(max(sb, 0), 2047);
        if (sb > sb1) acc += __expf((s - rm) * INV_T);
    }
    if (tid == 0) {
        int rem = need - above2;
        float smid = lo + ((float)sb1 + 0.5f) * (1.0f / (1024.0f * 2048.0f));
        acc += (float)rem * __expf((smid - rm) * INV_T);
    }

    // ---- random-negative gather: pure table lookup (no MUFU)
    const int2* ri2 = (const int2*)(ridx + (size_t)b * NRAND);
    for (int i = tid; i < NRAND / 2; i += SEL_T) {
        int2 p = __ldg(ri2 + i);
        acc += __half2float(srow[p.x]) + __half2float(srow[p.y]);
    }

    #pragma unroll
    for (int o = 16; o; o >>= 1) acc += __shfl_xor_sync(0xFFFFFFFFu, acc, o);
    if ((tid & 31) == 0) wred[tid >> 5] = acc;
    __syncthreads();
    if (tid == 0) {
        float tot = 0.0f;
        for (int w = 0; w < SEL_T/32; ++w) tot += wred[w];
        float p_sh = (g_pos[b] - rm) * INV_T;
        tot += __expf(p_sh);
        atomicAdd(&g_sums[0], (double)(logf(tot) - p_sh));
        atomicAdd(&g_sums[1], (g_pos[b] >= rm) ? 1.0 : 0.0);
    }
}

__global__ void k_final(float* out, int n) {
    if (n >= 1) out[0] = (float)(g_sums[0] / (double)BATCH);
    if (n >= 2) out[1] = (float)(g_sums[1] / (double)BATCH);
}

// ---------------------------------------------------------------------------
extern "C" void kernel_launch(void* const* d_in, const int* in_sizes, int n_in,
                              void* d_out, int out_size) {
    const float* eeg   = (const float*)d_in[0];
    const float* clip  = (const float*)d_in[1];
    const float* queue = (const float*)d_in[2];
    const int*   ridx  = (const int*)d_in[3];
    float* out = (float*)d_out;

    cudaFuncSetAttribute(k_gemm,   cudaFuncAttributeMaxDynamicSharedMemorySize, GEMM_SMEM);
    cudaFuncSetAttribute(k_select, cudaFuncAttributeMaxDynamicSharedMemorySize, SEL_SMEM);

    k_zero<<<1, 1>>>();
    k_norm<<<BATCH, 128>>>(eeg, clip);
    k_convq<<<QSIZE * DIM / 4 / 256, 256>>>(queue);
    k_gemm<<<dim3(QSIZE / 256, BATCH / 128), 256, GEMM_SMEM>>>();
    k_select<<<BATCH, SEL_T, SEL_SMEM>>>(ridx);
    k_final<<<1, 1>>>(out, out_size);
}

// round 7
// speedup vs baseline: 1.4119x; 1.0921x over previous
#include <cuda_runtime.h>
#include <cuda_bf16.h>
#include <cuda_fp16.h>
#include <cstdint>
#include <cstddef>

// Problem constants
#define BATCH   4096
#define DIM     512
#define QSIZE   32768
#define NHARD   9830
#define NRAND   22938
#define INV_T   (1.0f/0.07f)
#define KEXP    (INV_T * 1.44269504f)   // log2(e)/T

// -------- device scratch (static allocation; no cudaMalloc allowed) --------
__device__ __nv_bfloat16 g_eegn[BATCH * DIM];            // 4 MB
__device__ __nv_bfloat16 g_qbf[QSIZE * DIM];             // 32 MB
__device__ __half        g_neg[(size_t)BATCH * QSIZE];   // 256 MB
__device__ float         g_pos[BATCH];
__device__ double        g_sums[2];

// ---------------------------------------------------------------------------
__global__ void k_zero() { g_sums[0] = 0.0; g_sums[1] = 0.0; }

__global__ __launch_bounds__(128) void k_norm(const float* __restrict__ eeg,
                                              const float* __restrict__ clip) {
    int b = blockIdx.x, t = threadIdx.x;
    float4 e = ((const float4*)(eeg  + (size_t)b * DIM))[t];
    float4 c = ((const float4*)(clip + (size_t)b * DIM))[t];
    float se = e.x*e.x + e.y*e.y + e.z*e.z + e.w*e.w;
    float sc = c.x*c.x + c.y*c.y + c.z*c.z + c.w*c.w;
    float sd = e.x*c.x + e.y*c.y + e.z*c.z + e.w*c.w;
    #pragma unroll
    for (int o = 16; o; o >>= 1) {
        se += __shfl_down_sync(0xFFFFFFFFu, se, o);
        sc += __shfl_down_sync(0xFFFFFFFFu, sc, o);
        sd += __shfl_down_sync(0xFFFFFFFFu, sd, o);
    }
    __shared__ float rs[3][4];
    __shared__ float sInvE;
    int w = t >> 5, l = t & 31;
    if (l == 0) { rs[0][w] = se; rs[1][w] = sc; rs[2][w] = sd; }
    __syncthreads();
    if (t == 0) {
        float SE = rs[0][0] + rs[0][1] + rs[0][2] + rs[0][3];
        float SC = rs[1][0] + rs[1][1] + rs[1][2] + rs[1][3];
        float SD = rs[2][0] + rs[2][1] + rs[2][2] + rs[2][3];
        float ie = 1.0f / fmaxf(sqrtf(SE), 1e-12f);
        float ic = 1.0f / fmaxf(sqrtf(SC), 1e-12f);
        sInvE = ie;
        g_pos[b] = SD * ie * ic;
    }
    __syncthreads();
    float ie = sInvE;
    __nv_bfloat16* dst = g_eegn + (size_t)b * DIM + t * 4;
    dst[0] = __float2bfloat16(e.x * ie);
    dst[1] = __float2bfloat16(e.y * ie);
    dst[2] = __float2bfloat16(e.z * ie);
    dst[3] = __float2bfloat16(e.w * ie);
}

__global__ __launch_bounds__(256) void k_convq(const float* __restrict__ q) {
    int i = blockIdx.x * 256 + threadIdx.x;
    float4 v = ((const float4*)q)[i];
    __nv_bfloat162* d = (__nv_bfloat162*)g_qbf;
    d[2 * i]     = __floats2bfloat162_rn(v.x, v.y);
    d[2 * i + 1] = __floats2bfloat162_rn(v.z, v.w);
}

// ---------------------------------------------------------------------------
// mma.sync GEMM, CTA 128x256, 512 threads, warp tile 64x32 (2x8 warp grid),
// 6-stage cp.async, single-buffered fragments (TLP over ILP).
// ---------------------------------------------------------------------------
__device__ __forceinline__ uint32_t smem_u32(const void* p) {
    return (uint32_t)__cvta_generic_to_shared(p);
}
__device__ __forceinline__ void cp16(uint32_t s, const void* g) {
    asm volatile("cp.async.cg.shared.global [%0], [%1], 16;\n" :: "r"(s), "l"(g));
}
__device__ __forceinline__ void cp_commit() { asm volatile("cp.async.commit_group;\n"); }
template <int N> __device__ __forceinline__ void cp_wait() {
    asm volatile("cp.async.wait_group %0;\n" :: "n"(N));
}

#define LDSK 40                        // 32 + 8 pad elems: 80B rows
#define STAGES 6
#define KTILES 16                      // DIM / 32
#define A_STAGE_B (128 * LDSK * 2)     // 10240 B
#define B_STAGE_B (256 * LDSK * 2)     // 20480 B
#define STAGE_B   (A_STAGE_B + B_STAGE_B)
#define GEMM_SMEM (STAGES * STAGE_B)   // 184320 B

__global__ __launch_bounds__(512, 1) void k_gemm() {
    extern __shared__ __align__(16) unsigned char smraw[];
    uint32_t sbase = smem_u32(smraw);
    int tid = threadIdx.x, warp = tid >> 5, lane = tid & 31;
    int bn = blockIdx.x, bm = blockIdx.y;
    int wm = warp & 1, wn = warp >> 1;   // 2(m) x 8(n); warp tile 64x32

    const __nv_bfloat16* Abase = g_eegn + (size_t)bm * 128 * DIM;
    const __nv_bfloat16* Bbase = g_qbf  + (size_t)bn * 256 * DIM;

    auto load_stage = [&](int s, int kt) {
        uint32_t sa = sbase + s * STAGE_B;
        uint32_t sb = sa + A_STAGE_B;
        #pragma unroll
        for (int i = 0; i < 3; ++i) {               // 1536 16B chunks / 512 thr
            int c = tid + i * 512;
            uint32_t dst; const __nv_bfloat16* g; int row, col;
            if (c < 512) { row = c >> 2; col = c & 3; dst = sa;
                           g = Abase + (size_t)row * DIM + kt * 32 + col * 8; }
            else { int cb = c - 512; row = cb >> 2; col = cb & 3; dst = sb;
                   g = Bbase + (size_t)row * DIM + kt * 32 + col * 8; }
            cp16(dst + (uint32_t)(row * (LDSK * 2) + col * 16), g);
        }
    };

    float acc[4][4][4];
    #pragma unroll
    for (int i = 0; i < 4; i++)
        #pragma unroll
        for (int j = 0; j < 4; j++)
            #pragma unroll
            for (int r = 0; r < 4; r++) acc[i][j][r] = 0.0f;

    // A: 4x ldmatrix.x4 per ks (64 rows x 16k). B: 2x ldmatrix.x4 per ks (32 rows x 16k).
    int aRow = wm * 64 + (lane & 15);
    int aK0  = (lane >> 4) * 8;
    int bRow = wn * 32 + (lane & 7) + ((lane & 16) >> 1);
    int bK0  = ((lane >> 3) & 1) * 8;

    #pragma unroll
    for (int s = 0; s < STAGES - 1; ++s) { load_stage(s, s); cp_commit(); }

    for (int kt = 0; kt < KTILES; ++kt) {
        cp_wait<STAGES - 2>();
        __syncthreads();
        if (kt + STAGES - 1 < KTILES) load_stage((kt + STAGES - 1) % STAGES, kt + STAGES - 1);
        cp_commit();

        uint32_t sa = sbase + (kt % STAGES) * STAGE_B;
        uint32_t sb = sa + A_STAGE_B;
        #pragma unroll
        for (int ks = 0; ks < 2; ++ks) {
            uint32_t fa[4][4];
            #pragma unroll
            for (int mi = 0; mi < 4; mi++) {
                uint32_t addr = sa + (uint32_t)((aRow + mi * 16) * (LDSK * 2)
                                                + (ks * 16 + aK0) * 2);
                asm volatile("ldmatrix.sync.aligned.m8n8.x4.shared.b16 {%0,%1,%2,%3}, [%4];\n"
                    : "=r"(fa[mi][0]), "=r"(fa[mi][1]),
                      "=r"(fa[mi][2]), "=r"(fa[mi][3]) : "r"(addr));
            }
            uint32_t fb[2][4];
            #pragma unroll
            for (int np = 0; np < 2; np++) {
                uint32_t addr = sb + (uint32_t)((bRow + np * 16) * (LDSK * 2)
                                                + (ks * 16 + bK0) * 2);
                asm volatile("ldmatrix.sync.aligned.m8n8.x4.shared.b16 {%0,%1,%2,%3}, [%4];\n"
                    : "=r"(fb[np][0]), "=r"(fb[np][1]),
                      "=r"(fb[np][2]), "=r"(fb[np][3]) : "r"(addr));
            }
            #pragma unroll
            for (int mi = 0; mi < 4; mi++)
                #pragma unroll
                for (int ni = 0; ni < 4; ni++) {
                    uint32_t b0 = fb[ni >> 1][(ni & 1) * 2 + 0];
                    uint32_t b1 = fb[ni >> 1][(ni & 1) * 2 + 1];
                    asm volatile(
                        "mma.sync.aligned.m16n8k16.row.col.f32.bf16.bf16.f32 "
                        "{%0,%1,%2,%3}, {%4,%5,%6,%7}, {%8,%9}, {%0,%1,%2,%3};\n"
                        : "+f"(acc[mi][ni][0]), "+f"(acc[mi][ni][1]),
                          "+f"(acc[mi][ni][2]), "+f"(acc[mi][ni][3])
                        : "r"(fa[mi][0]), "r"(fa[mi][1]),
                          "r"(fa[mi][2]), "r"(fa[mi][3]),
                          "r"(b0), "r"(b1));
                }
        }
    }

    // Epilogue: fp32 -> fp16 store
    #pragma unroll
    for (int mi = 0; mi < 4; mi++) {
        #pragma unroll
        for (int ni = 0; ni < 4; ni++) {
            int row = bm * 128 + wm * 64 + mi * 16 + (lane >> 2);
            int col = bn * 256 + wn * 32 + ni * 8 + (lane & 3) * 2;
            *(__half2*)&g_neg[(size_t)row * QSIZE + col] =
                __floats2half2_rn(acc[mi][ni][0], acc[mi][ni][1]);
            *(__half2*)&g_neg[(size_t)(row + 8) * QSIZE + col] =
                __floats2half2_rn(acc[mi][ni][2], acc[mi][ni][3]);
        }
    }
}

// ---------------------------------------------------------------------------
// k_select: pass1 (load+max+hist), fused pass2 (f16x2 exp + exp-table), gather.
// All exp sums in scaled domain e^((s-rowmax)/T).
// ---------------------------------------------------------------------------
#define SEL_T 512
#define CBUF_CAP 8192
#define SEL_SMEM (QSIZE*2 + 2048*4 + CBUF_CAP*2)

__device__ __forceinline__ uint32_t h2ex2(uint32_t x) {
    uint32_t r;
    asm("ex2.approx.f16x2 %0, %1;" : "=r"(r) : "r"(x));
    return r;
}

__device__ __forceinline__ void find_bin(int* hist, int target, int* scs,
                                         int* out_bin, int* out_above, int tid) {
    int base = tid * 4;
    int c = hist[base] + hist[base+1] + hist[base+2] + hist[base+3];
    scs[tid] = c;
    __syncthreads();
    #pragma unroll
    for (int d = 1; d < SEL_T; d <<= 1) {
        int v = (tid + d < SEL_T) ? scs[tid + d] : 0;
        __syncthreads();
        scs[tid] += v;
        __syncthreads();
    }
    int Sincl = scs[tid];
    int Sexcl = (tid + 1 < SEL_T) ? scs[tid + 1] : 0;
    if (Sexcl < target && Sincl >= target) {
        int ca = Sexcl;
        #pragma unroll
        for (int j = 3; j >= 0; --j) {
            int h = hist[base + j];
            if (ca + h >= target) { *out_bin = base + j; *out_above = ca; break; }
            ca += h;
        }
    }
}

__global__ __launch_bounds__(SEL_T) void k_select(const int* __restrict__ ridx) {
    extern __shared__ unsigned char dyn2[];
    __half*  srow  = (__half*)dyn2;                         // 65536 B
    __half2* srow2 = (__half2*)dyn2;
    int*     hist  = (int*)(dyn2 + QSIZE*2);                // 8192 B
    __half*  cbuf  = (__half*)(dyn2 + QSIZE*2 + 2048*4);    // 16384 B
    __shared__ int   scs[SEL_T];
    __shared__ float wred[SEL_T/32];
    __shared__ int   s_bin, s_above, s_nc;
    __shared__ float s_max;

    int b = blockIdx.x, tid = threadIdx.x;

    for (int i = tid; i < 2048; i += SEL_T) hist[i] = 0;
    if (tid == 0) s_nc = 0;
    __syncthreads();

    // ---- pass 1: load row, rowmax (f16 pairwise), level-1 histogram
    const uint4* src = (const uint4*)(g_neg + (size_t)b * QSIZE);
    uint4* drow = (uint4*)srow;
    __half2 hm = __floats2half2_rn(-2.0f, -2.0f);
    for (int i = tid; i < QSIZE / 8; i += SEL_T) {
        uint4 v = src[i]; drow[i] = v;
        uint32_t ws[4] = {v.x, v.y, v.z, v.w};
        #pragma unroll
        for (int q = 0; q < 4; ++q) {
            __half2 h2 = *(__half2*)&ws[q];
            hm = __hmax2(hm, h2);
            float2 f = __half22float2(h2);
            int b0 = (int)((f.x + 1.0f) * 1024.0f); b0 = min(max(b0, 0), 2047);
            int b1 = (int)((f.y + 1.0f) * 1024.0f); b1 = min(max(b1, 0), 2047);
            atomicAdd(&hist[b0], 1);
            atomicAdd(&hist[b1], 1);
        }
    }
    float lmax = fmaxf(__low2float(hm), __high2float(hm));
    #pragma unroll
    for (int o = 16; o; o >>= 1) lmax = fmaxf(lmax, __shfl_xor_sync(0xFFFFFFFFu, lmax, o));
    if ((tid & 31) == 0) wred[tid >> 5] = lmax;
    __syncthreads();
    if (tid == 0) {
        float m = -2.0f;
        for (int w = 0; w < SEL_T/32; ++w) m = fmaxf(m, wred[w]);
        s_max = m;
    }
    __syncthreads();
    float rm = s_max;

    find_bin(hist, NHARD, scs, &s_bin, &s_above, tid);
    __syncthreads();
    int bin1 = s_bin, need = NHARD - s_above;
    float lo = (float)bin1 * (1.0f / 1024.0f) - 1.0f;
    __syncthreads();

    // ---- pass 2 (fused): masked scaled-exp sum, boundary compaction,
    //      overwrite srow with e^((s-rm)/T) as the gather table.
    float accx = 0.0f, accy = 0.0f;
    for (int i = tid; i < QSIZE / 2; i += SEL_T) {
        __half2 v2 = srow2[i];
        float2 f = __half22float2(v2);
        int b0 = (int)((f.x + 1.0f) * 1024.0f); b0 = min(max(b0, 0), 2047);
        int b1 = (int)((f.y + 1.0f) * 1024.0f); b1 = min(max(b1, 0), 2047);
        if (b0 == bin1) { int p = atomicAdd(&s_nc, 1); if (p < CBUF_CAP) cbuf[p] = __low2half(v2); }
        if (b1 == bin1) { int p = atomicAdd(&s_nc, 1); if (p < CBUF_CAP) cbuf[p] = __high2half(v2); }
        __half2 xh = __floats2half2_rn((f.x - rm) * KEXP, (f.y - rm) * KEXP);
        uint32_t eu = h2ex2(*(uint32_t*)&xh);
        __half2 e2 = *(__half2*)&eu;
        float2 ef = __half22float2(e2);
        if (b0 > bin1) accx += ef.x;
        if (b1 > bin1) accy += ef.y;
        srow2[i] = e2;
    }
    float acc = accx + accy;
    __syncthreads();

    // ---- level 2 on the compacted boundary bin
    int nc = min(s_nc, CBUF_CAP);
    for (int i = tid; i < 2048; i += SEL_T) hist[i] = 0;
    __syncthreads();
    for (int i = tid; i < nc; i += SEL_T) {
        float s = __half2float(cbuf[i]);
        int sb = (int)((s - lo) * (1024.0f * 2048.0f)); sb = min(max(sb, 0), 2047);
        atomicAdd(&hist[sb], 1);
    }
    __syncthreads();
    find_bin(hist, need, scs, &s_bin, &s_above, tid);
    __syncthreads();
    int sb1 = s_bin, above2 = s_above;
    for (int i = tid; i < nc; i += SEL_T) {
        float s = __half2float(cbuf[i]);
        int sb = (int)((s - lo) * (1024.0f * 2048.0f)); sb = min(max(sb, 0), 2047);
        if (sb > sb1) acc += __expf((s - rm) * INV_T);
    }
    if (tid == 0) {
        int rem = need - above2;
        float smid = lo + ((float)sb1 + 0.5f) * (1.0f / (1024.0f * 2048.0f));
        acc += (float)rem * __expf((smid - rm) * INV_T);
    }

    // ---- random-negative gather: pure table lookup (no MUFU)
    const int2* ri2 = (const int2*)(ridx + (size_t)b * NRAND);
    for (int i = tid; i < NRAND / 2; i += SEL_T) {
        int2 p = __ldg(ri2 + i);
        acc += __half2float(srow[p.x]) + __half2float(srow[p.y]);
    }

    #pragma unroll
    for (int o = 16; o; o >>= 1) acc += __shfl_xor_sync(0xFFFFFFFFu, acc, o);
    if ((tid & 31) == 0) wred[tid >> 5] = acc;
    __syncthreads();
    if (tid == 0) {
        float tot = 0.0f;
        for (int w = 0; w < SEL_T/32; ++w) tot += wred[w];
        float p_sh = (g_pos[b] - rm) * INV_T;
        tot += __expf(p_sh);
        atomicAdd(&g_sums[0], (double)(logf(tot) - p_sh));
        atomicAdd(&g_sums[1], (g_pos[b] >= rm) ? 1.0 : 0.0);
    }
}

__global__ void k_final(float* out, int n) {
    if (n >= 1) out[0] = (float)(g_sums[0] / (double)BATCH);
    if (n >= 2) out[1] = (float)(g_sums[1] / (double)BATCH);
}

// ---------------------------------------------------------------------------
extern "C" void kernel_launch(void* const* d_in, const int* in_sizes, int n_in,
                              void* d_out, int out_size) {
    const float* eeg   = (const float*)d_in[0];
    const float* clip  = (const float*)d_in[1];
    const float* queue = (const float*)d_in[2];
    const int*   ridx  = (const int*)d_in[3];
    float* out = (float*)d_out;

    cudaFuncSetAttribute(k_gemm,   cudaFuncAttributeMaxDynamicSharedMemorySize, GEMM_SMEM);
    cudaFuncSetAttribute(k_select, cudaFuncAttributeMaxDynamicSharedMemorySize, SEL_SMEM);

    k_zero<<<1, 1>>>();
    k_norm<<<BATCH, 128>>>(eeg, clip);
    k_convq<<<QSIZE * DIM / 4 / 256, 256>>>(queue);
    k_gemm<<<dim3(QSIZE / 256, BATCH / 128), 512, GEMM_SMEM>>>();
    k_select<<<BATCH, SEL_T, SEL_SMEM>>>(ridx);
    k_final<<<1, 1>>>(out, out_size);
}

// round 8
// speedup vs baseline: 1.4149x; 1.0021x over previous
#include <cuda_runtime.h>
#include <cuda_bf16.h>
#include <cuda_fp16.h>
#include <cstdint>
#include <cstddef>

// Problem constants
#define BATCH   4096
#define DIM     512
#define QSIZE   32768
#define NHARD   9830
#define NRAND   22938
#define INV_T   (1.0f/0.07f)
#define KEXP    (INV_T * 1.44269504f)   // log2(e)/T

// -------- device scratch (static allocation; no cudaMalloc allowed) --------
__device__ __half  g_eegn[BATCH * DIM];            // 4 MB  normalized eeg, fp16
__device__ __half  g_qbf[QSIZE * DIM];             // 32 MB queue, fp16
__device__ __half  g_neg[(size_t)BATCH * QSIZE];   // 256 MB
__device__ float   g_pos[BATCH];
__device__ double  g_sums[2];

// ---------------------------------------------------------------------------
__global__ void k_zero() { g_sums[0] = 0.0; g_sums[1] = 0.0; }

__global__ __launch_bounds__(128) void k_norm(const float* __restrict__ eeg,
                                              const float* __restrict__ clip) {
    int b = blockIdx.x, t = threadIdx.x;
    float4 e = ((const float4*)(eeg  + (size_t)b * DIM))[t];
    float4 c = ((const float4*)(clip + (size_t)b * DIM))[t];
    float se = e.x*e.x + e.y*e.y + e.z*e.z + e.w*e.w;
    float sc = c.x*c.x + c.y*c.y + c.z*c.z + c.w*c.w;
    float sd = e.x*c.x + e.y*c.y + e.z*c.z + e.w*c.w;
    #pragma unroll
    for (int o = 16; o; o >>= 1) {
        se += __shfl_down_sync(0xFFFFFFFFu, se, o);
        sc += __shfl_down_sync(0xFFFFFFFFu, sc, o);
        sd += __shfl_down_sync(0xFFFFFFFFu, sd, o);
    }
    __shared__ float rs[3][4];
    __shared__ float sInvE;
    int w = t >> 5, l = t & 31;
    if (l == 0) { rs[0][w] = se; rs[1][w] = sc; rs[2][w] = sd; }
    __syncthreads();
    if (t == 0) {
        float SE = rs[0][0] + rs[0][1] + rs[0][2] + rs[0][3];
        float SC = rs[1][0] + rs[1][1] + rs[1][2] + rs[1][3];
        float SD = rs[2][0] + rs[2][1] + rs[2][2] + rs[2][3];
        float ie = 1.0f / fmaxf(sqrtf(SE), 1e-12f);
        float ic = 1.0f / fmaxf(sqrtf(SC), 1e-12f);
        sInvE = ie;
        g_pos[b] = SD * ie * ic;
    }
    __syncthreads();
    float ie = sInvE;
    __half* dst = g_eegn + (size_t)b * DIM + t * 4;
    dst[0] = __float2half(e.x * ie);
    dst[1] = __float2half(e.y * ie);
    dst[2] = __float2half(e.z * ie);
    dst[3] = __float2half(e.w * ie);
}

__global__ __launch_bounds__(256) void k_convq(const float* __restrict__ q) {
    int i = blockIdx.x * 256 + threadIdx.x;
    float4 v = ((const float4*)q)[i];
    __half2* d = (__half2*)g_qbf;
    d[2 * i]     = __floats2half2_rn(v.x, v.y);
    d[2 * i + 1] = __floats2half2_rn(v.z, v.w);
}

// ---------------------------------------------------------------------------
// mma.sync fp16 GEMM with f16 accumulate.
// CTA tile 256x256, 512 threads, warp grid 4x4, warp tile 64x64.
// 5-stage cp.async. Fragment smem traffic: 625 cyc/unit < tensor 1024.
// ---------------------------------------------------------------------------
__device__ __forceinline__ uint32_t smem_u32(const void* p) {
    return (uint32_t)__cvta_generic_to_shared(p);
}
__device__ __forceinline__ void cp16(uint32_t s, const void* g) {
    asm volatile("cp.async.cg.shared.global [%0], [%1], 16;\n" :: "r"(s), "l"(g));
}
__device__ __forceinline__ void cp_commit() { asm volatile("cp.async.commit_group;\n"); }
template <int N> __device__ __forceinline__ void cp_wait() {
    asm volatile("cp.async.wait_group %0;\n" :: "n"(N));
}

#define LDSK 40                        // 32 + 8 pad elems: 80B rows
#define STAGES 5
#define KTILES 16                      // DIM / 32
#define A_STAGE_B (256 * LDSK * 2)     // 20480 B
#define B_STAGE_B (256 * LDSK * 2)     // 20480 B
#define STAGE_B   (A_STAGE_B + B_STAGE_B)
#define GEMM_SMEM (STAGES * STAGE_B)   // 204800 B

__global__ __launch_bounds__(512, 1) void k_gemm() {
    extern __shared__ __align__(16) unsigned char smraw[];
    uint32_t sbase = smem_u32(smraw);
    int tid = threadIdx.x, warp = tid >> 5, lane = tid & 31;
    int bn = blockIdx.x, bm = blockIdx.y;
    int wm = warp & 3, wn = warp >> 2;   // 4(m) x 4(n); warp tile 64x64

    const __half* Abase = g_eegn + (size_t)bm * 256 * DIM;
    const __half* Bbase = g_qbf  + (size_t)bn * 256 * DIM;

    auto load_stage = [&](int s, int kt) {
        uint32_t sa = sbase + s * STAGE_B;
        uint32_t sb = sa + A_STAGE_B;
        #pragma unroll
        for (int i = 0; i < 4; ++i) {               // 2048 16B chunks / 512 thr
            int c = tid + i * 512;
            uint32_t dst; const __half* g; int row, col;
            if (c < 1024) { row = c >> 2; col = c & 3; dst = sa;
                            g = Abase + (size_t)row * DIM + kt * 32 + col * 8; }
            else { int cb = c - 1024; row = cb >> 2; col = cb & 3; dst = sb;
                   g = Bbase + (size_t)row * DIM + kt * 32 + col * 8; }
            cp16(dst + (uint32_t)(row * (LDSK * 2) + col * 16), g);
        }
    };

    uint32_t acc[4][8][2];               // f16x2 accumulators
    #pragma unroll
    for (int i = 0; i < 4; i++)
        #pragma unroll
        for (int j = 0; j < 8; j++) { acc[i][j][0] = 0u; acc[i][j][1] = 0u; }

    // A: 4x ldmatrix.x4 per ks (64 rows x 16k). B: 4x ldmatrix.x4 (64 rows x 16k).
    int aRow = wm * 64 + (lane & 15);
    int aK0  = (lane >> 4) * 8;
    int bRow = wn * 64 + (lane & 7) + ((lane & 16) >> 1);
    int bK0  = ((lane >> 3) & 1) * 8;

    #pragma unroll
    for (int s = 0; s < STAGES - 1; ++s) { load_stage(s, s); cp_commit(); }

    for (int kt = 0; kt < KTILES; ++kt) {
        cp_wait<STAGES - 2>();
        __syncthreads();
        if (kt + STAGES - 1 < KTILES) load_stage((kt + STAGES - 1) % STAGES, kt + STAGES - 1);
        cp_commit();

        uint32_t sa = sbase + (kt % STAGES) * STAGE_B;
        uint32_t sb = sa + A_STAGE_B;
        #pragma unroll
        for (int ks = 0; ks < 2; ++ks) {
            uint32_t fa[4][4];
            #pragma unroll
            for (int mi = 0; mi < 4; mi++) {
                uint32_t addr = sa + (uint32_t)((aRow + mi * 16) * (LDSK * 2)
                                                + (ks * 16 + aK0) * 2);
                asm volatile("ldmatrix.sync.aligned.m8n8.x4.shared.b16 {%0,%1,%2,%3}, [%4];\n"
                    : "=r"(fa[mi][0]), "=r"(fa[mi][1]),
                      "=r"(fa[mi][2]), "=r"(fa[mi][3]) : "r"(addr));
            }
            uint32_t fb[4][4];
            #pragma unroll
            for (int np = 0; np < 4; np++) {
                uint32_t addr = sb + (uint32_t)((bRow + np * 16) * (LDSK * 2)
                                                + (ks * 16 + bK0) * 2);
                asm volatile("ldmatrix.sync.aligned.m8n8.x4.shared.b16 {%0,%1,%2,%3}, [%4];\n"
                    : "=r"(fb[np][0]), "=r"(fb[np][1]),
                      "=r"(fb[np][2]), "=r"(fb[np][3]) : "r"(addr));
            }
            #pragma unroll
            for (int mi = 0; mi < 4; mi++)
                #pragma unroll
                for (int ni = 0; ni < 8; ni++) {
                    uint32_t b0 = fb[ni >> 1][(ni & 1) * 2 + 0];
                    uint32_t b1 = fb[ni >> 1][(ni & 1) * 2 + 1];
                    asm volatile(
                        "mma.sync.aligned.m16n8k16.row.col.f16.f16.f16.f16 "
                        "{%0,%1}, {%2,%3,%4,%5}, {%6,%7}, {%0,%1};\n"
                        : "+r"(acc[mi][ni][0]), "+r"(acc[mi][ni][1])
                        : "r"(fa[mi][0]), "r"(fa[mi][1]),
                          "r"(fa[mi][2]), "r"(fa[mi][3]),
                          "r"(b0), "r"(b1));
                }
        }
    }

    // Epilogue: accumulators are already packed fp16 pairs -> direct store
    #pragma unroll
    for (int mi = 0; mi < 4; mi++) {
        #pragma unroll
        for (int ni = 0; ni < 8; ni++) {
            int row = bm * 256 + wm * 64 + mi * 16 + (lane >> 2);
            int col = bn * 256 + wn * 64 + ni * 8 + (lane & 3) * 2;
            *(uint32_t*)&g_neg[(size_t)row * QSIZE + col]       = acc[mi][ni][0];
            *(uint32_t*)&g_neg[(size_t)(row + 8) * QSIZE + col] = acc[mi][ni][1];
        }
    }
}

// ---------------------------------------------------------------------------
// k_select: pass1 (load+max+hist), fused pass2 (f16x2 exp + exp-table), gather.
// All exp sums in scaled domain e^((s-rowmax)/T).
// ---------------------------------------------------------------------------
#define SEL_T 512
#define CBUF_CAP 8192
#define SEL_SMEM (QSIZE*2 + 2048*4 + CBUF_CAP*2)

__device__ __forceinline__ uint32_t h2ex2(uint32_t x) {
    uint32_t r;
    asm("ex2.approx.f16x2 %0, %1;" : "=r"(r) : "r"(x));
    return r;
}

__device__ __forceinline__ void find_bin(int* hist, int target, int* scs,
                                         int* out_bin, int* out_above, int tid) {
    int base = tid * 4;
    int c = hist[base] + hist[base+1] + hist[base+2] + hist[base+3];
    scs[tid] = c;
    __syncthreads();
    #pragma unroll
    for (int d = 1; d < SEL_T; d <<= 1) {
        int v = (tid + d < SEL_T) ? scs[tid + d] : 0;
        __syncthreads();
        scs[tid] += v;
        __syncthreads();
    }
    int Sincl = scs[tid];
    int Sexcl = (tid + 1 < SEL_T) ? scs[tid + 1] : 0;
    if (Sexcl < target && Sincl >= target) {
        int ca = Sexcl;
        #pragma unroll
        for (int j = 3; j >= 0; --j) {
            int h = hist[base + j];
            if (ca + h >= target) { *out_bin = base + j; *out_above = ca; break; }
            ca += h;
        }
    }
}

__global__ __launch_bounds__(SEL_T) void k_select(const int* __restrict__ ridx) {
    extern __shared__ unsigned char dyn2[];
    __half*  srow  = (__half*)dyn2;                         // 65536 B
    __half2* srow2 = (__half2*)dyn2;
    int*     hist  = (int*)(dyn2 + QSIZE*2);                // 8192 B
    __half*  cbuf  = (__half*)(dyn2 + QSIZE*2 + 2048*4);    // 16384 B
    __shared__ int   scs[SEL_T];
    __shared__ float wred[SEL_T/32];
    __shared__ int   s_bin, s_above, s_nc;
    __shared__ float s_max;

    int b = blockIdx.x, tid = threadIdx.x;

    for (int i = tid; i < 2048; i += SEL_T) hist[i] = 0;
    if (tid == 0) s_nc = 0;
    __syncthreads();

    // ---- pass 1: load row, rowmax (f16 pairwise), level-1 histogram
    const uint4* src = (const uint4*)(g_neg + (size_t)b * QSIZE);
    uint4* drow = (uint4*)srow;
    __half2 hm = __floats2half2_rn(-2.0f, -2.0f);
    for (int i = tid; i < QSIZE / 8; i += SEL_T) {
        uint4 v = src[i]; drow[i] = v;
        uint32_t ws[4] = {v.x, v.y, v.z, v.w};
        #pragma unroll
        for (int q = 0; q < 4; ++q) {
            __half2 h2 = *(__half2*)&ws[q];
            hm = __hmax2(hm, h2);
            float2 f = __half22float2(h2);
            int b0 = (int)((f.x + 1.0f) * 1024.0f); b0 = min(max(b0, 0), 2047);
            int b1 = (int)((f.y + 1.0f) * 1024.0f); b1 = min(max(b1, 0), 2047);
            atomicAdd(&hist[b0], 1);
            atomicAdd(&hist[b1], 1);
        }
    }
    float lmax = fmaxf(__low2float(hm), __high2float(hm));
    #pragma unroll
    for (int o = 16; o; o >>= 1) lmax = fmaxf(lmax, __shfl_xor_sync(0xFFFFFFFFu, lmax, o));
    if ((tid & 31) == 0) wred[tid >> 5] = lmax;
    __syncthreads();
    if (tid == 0) {
        float m = -2.0f;
        for (int w = 0; w < SEL_T/32; ++w) m = fmaxf(m, wred[w]);
        s_max = m;
    }
    __syncthreads();
    float rm = s_max;

    find_bin(hist, NHARD, scs, &s_bin, &s_above, tid);
    __syncthreads();
    int bin1 = s_bin, need = NHARD - s_above;
    float lo = (float)bin1 * (1.0f / 1024.0f) - 1.0f;
    __syncthreads();

    // ---- pass 2 (fused): masked scaled-exp sum, boundary compaction,
    //      overwrite srow with e^((s-rm)/T) as the gather table.
    float accx = 0.0f, accy = 0.0f;
    for (int i = tid; i < QSIZE / 2; i += SEL_T) {
        __half2 v2 = srow2[i];
        float2 f = __half22float2(v2);
        int b0 = (int)((f.x + 1.0f) * 1024.0f); b0 = min(max(b0, 0), 2047);
        int b1 = (int)((f.y + 1.0f) * 1024.0f); b1 = min(max(b1, 0), 2047);
        if (b0 == bin1) { int p = atomicAdd(&s_nc, 1); if (p < CBUF_CAP) cbuf[p] = __low2half(v2); }
        if (b1 == bin1) { int p = atomicAdd(&s_nc, 1); if (p < CBUF_CAP) cbuf[p] = __high2half(v2); }
        __half2 xh = __floats2half2_rn((f.x - rm) * KEXP, (f.y - rm) * KEXP);
        uint32_t eu = h2ex2(*(uint32_t*)&xh);
        __half2 e2 = *(__half2*)&eu;
        float2 ef = __half22float2(e2);
        if (b0 > bin1) accx += ef.x;
        if (b1 > bin1) accy += ef.y;
        srow2[i] = e2;
    }
    float acc = accx + accy;
    __syncthreads();

    // ---- level 2 on the compacted boundary bin
    int nc = min(s_nc, CBUF_CAP);
    for (int i = tid; i < 2048; i += SEL_T) hist[i] = 0;
    __syncthreads();
    for (int i = tid; i < nc; i += SEL_T) {
        float s = __half2float(cbuf[i]);
        int sb = (int)((s - lo) * (1024.0f * 2048.0f)); sb = min(max(sb, 0), 2047);
        atomicAdd(&hist[sb], 1);
    }
    __syncthreads();
    find_bin(hist, need, scs, &s_bin, &s_above, tid);
    __syncthreads();
    int sb1 = s_bin, above2 = s_above;
    for (int i = tid; i < nc; i += SEL_T) {
        float s = __half2float(cbuf[i]);
        int sb = (int)((s - lo) * (1024.0f * 2048.0f)); sb = min(max(sb, 0), 2047);
        if (sb > sb1) acc += __expf((s - rm) * INV_T);
    }
    if (tid == 0) {
        int rem = need - above2;
        float smid = lo + ((float)sb1 + 0.5f) * (1.0f / (1024.0f * 2048.0f));
        acc += (float)rem * __expf((smid - rm) * INV_T);
    }

    // ---- random-negative gather: pure table lookup (no MUFU)
    const int2* ri2 = (const int2*)(ridx + (size_t)b * NRAND);
    for (int i = tid; i < NRAND / 2; i += SEL_T) {
        int2 p = __ldg(ri2 + i);
        acc += __half2float(srow[p.x]) + __half2float(srow[p.y]);
    }

    #pragma unroll
    for (int o = 16; o; o >>= 1) acc += __shfl_xor_sync(0xFFFFFFFFu, acc, o);
    if ((tid & 31) == 0) wred[tid >> 5] = acc;
    __syncthreads();
    if (tid == 0) {
        float tot = 0.0f;
        for (int w = 0; w < SEL_T/32; ++w) tot += wred[w];
        float p_sh = (g_pos[b] - rm) * INV_T;
        tot += __expf(p_sh);
        atomicAdd(&g_sums[0], (double)(logf(tot) - p_sh));
        atomicAdd(&g_sums[1], (g_pos[b] >= rm) ? 1.0 : 0.0);
    }
}

__global__ void k_final(float* out, int n) {
    if (n >= 1) out[0] = (float)(g_sums[0] / (double)BATCH);
    if (n >= 2) out[1] = (float)(g_sums[1] / (double)BATCH);
}

// ---------------------------------------------------------------------------
extern "C" void kernel_launch(void* const* d_in, const int* in_sizes, int n_in,
                              void* d_out, int out_size) {
    const float* eeg   = (const float*)d_in[0];
    const float* clip  = (const float*)d_in[1];
    const float* queue = (const float*)d_in[2];
    const int*   ridx  = (const int*)d_in[3];
    float* out = (float*)d_out;

    cudaFuncSetAttribute(k_gemm,   cudaFuncAttributeMaxDynamicSharedMemorySize, GEMM_SMEM);
    cudaFuncSetAttribute(k_select, cudaFuncAttributeMaxDynamicSharedMemorySize, SEL_SMEM);

    k_zero<<<1, 1>>>();
    k_norm<<<BATCH, 128>>>(eeg, clip);
    k_convq<<<QSIZE * DIM / 4 / 256, 256>>>(queue);
    k_gemm<<<dim3(QSIZE / 256, BATCH / 256), 512, GEMM_SMEM>>>();
    k_select<<<BATCH, SEL_T, SEL_SMEM>>>(ridx);
    k_final<<<1, 1>>>(out, out_size);
}

// round 9
// speedup vs baseline: 1.4552x; 1.0285x over previous
#include <cuda_runtime.h>
#include <cuda_bf16.h>
#include <cuda_fp16.h>
#include <cstdint>
#include <cstddef>

// Problem constants
#define BATCH   4096
#define DIM     512
#define QSIZE   32768
#define NHARD   9830
#define NRAND   22938
#define INV_T   (1.0f/0.07f)
#define KEXP    (INV_T * 1.44269504f)   // log2(e)/T

// -------- device scratch (static allocation; no cudaMalloc allowed) --------
__device__ __half  g_eegn[BATCH * DIM];            // 4 MB  normalized eeg, fp16
__device__ __half  g_qbf[QSIZE * DIM];             // 32 MB queue, fp16
__device__ __half  g_neg[(size_t)BATCH * QSIZE];   // 256 MB
__device__ float   g_pos[BATCH];
__device__ double  g_sums[2];

// ---------------------------------------------------------------------------
__global__ void k_zero() { g_sums[0] = 0.0; g_sums[1] = 0.0; }

__global__ __launch_bounds__(128) void k_norm(const float* __restrict__ eeg,
                                              const float* __restrict__ clip) {
    int b = blockIdx.x, t = threadIdx.x;
    float4 e = ((const float4*)(eeg  + (size_t)b * DIM))[t];
    float4 c = ((const float4*)(clip + (size_t)b * DIM))[t];
    float se = e.x*e.x + e.y*e.y + e.z*e.z + e.w*e.w;
    float sc = c.x*c.x + c.y*c.y + c.z*c.z + c.w*c.w;
    float sd = e.x*c.x + e.y*c.y + e.z*c.z + e.w*c.w;
    #pragma unroll
    for (int o = 16; o; o >>= 1) {
        se += __shfl_down_sync(0xFFFFFFFFu, se, o);
        sc += __shfl_down_sync(0xFFFFFFFFu, sc, o);
        sd += __shfl_down_sync(0xFFFFFFFFu, sd, o);
    }
    __shared__ float rs[3][4];
    __shared__ float sInvE;
    int w = t >> 5, l = t & 31;
    if (l == 0) { rs[0][w] = se; rs[1][w] = sc; rs[2][w] = sd; }
    __syncthreads();
    if (t == 0) {
        float SE = rs[0][0] + rs[0][1] + rs[0][2] + rs[0][3];
        float SC = rs[1][0] + rs[1][1] + rs[1][2] + rs[1][3];
        float SD = rs[2][0] + rs[2][1] + rs[2][2] + rs[2][3];
        float ie = 1.0f / fmaxf(sqrtf(SE), 1e-12f);
        float ic = 1.0f / fmaxf(sqrtf(SC), 1e-12f);
        sInvE = ie;
        g_pos[b] = SD * ie * ic;
    }
    __syncthreads();
    float ie = sInvE;
    __half* dst = g_eegn + (size_t)b * DIM + t * 4;
    dst[0] = __float2half(e.x * ie);
    dst[1] = __float2half(e.y * ie);
    dst[2] = __float2half(e.z * ie);
    dst[3] = __float2half(e.w * ie);
}

__global__ __launch_bounds__(256) void k_convq(const float* __restrict__ q) {
    int i = blockIdx.x * 256 + threadIdx.x;
    float4 v = ((const float4*)q)[i];
    __half2* d = (__half2*)g_qbf;
    d[2 * i]     = __floats2half2_rn(v.x, v.y);
    d[2 * i + 1] = __floats2half2_rn(v.z, v.w);
}

// ---------------------------------------------------------------------------
// mma.sync fp16 GEMM, f16 accumulate.
// CTA tile 128x256, 256 threads, warp grid 2x4, warp tile 64x64.
// 3-stage cp.async, 92KB smem -> 2 CTAs/SM (barrier drains overlap).
// ---------------------------------------------------------------------------
__device__ __forceinline__ uint32_t smem_u32(const void* p) {
    return (uint32_t)__cvta_generic_to_shared(p);
}
__device__ __forceinline__ void cp16(uint32_t s, const void* g) {
    asm volatile("cp.async.cg.shared.global [%0], [%1], 16;\n" :: "r"(s), "l"(g));
}
__device__ __forceinline__ void cp_commit() { asm volatile("cp.async.commit_group;\n"); }
template <int N> __device__ __forceinline__ void cp_wait() {
    asm volatile("cp.async.wait_group %0;\n" :: "n"(N));
}

#define LDSK 40                        // 32 + 8 pad elems: 80B rows
#define STAGES 3
#define KTILES 16                      // DIM / 32
#define A_STAGE_B (128 * LDSK * 2)     // 10240 B
#define B_STAGE_B (256 * LDSK * 2)     // 20480 B
#define STAGE_B   (A_STAGE_B + B_STAGE_B)
#define GEMM_SMEM (STAGES * STAGE_B)   // 92160 B -> 2 CTAs/SM

__global__ __launch_bounds__(256, 2) void k_gemm() {
    extern __shared__ __align__(16) unsigned char smraw[];
    uint32_t sbase = smem_u32(smraw);
    int tid = threadIdx.x, warp = tid >> 5, lane = tid & 31;
    int bn = blockIdx.x, bm = blockIdx.y;
    int wm = warp & 1, wn = warp >> 1;   // 2(m) x 4(n); warp tile 64x64

    const __half* Abase = g_eegn + (size_t)bm * 128 * DIM;
    const __half* Bbase = g_qbf  + (size_t)bn * 256 * DIM;

    auto load_stage = [&](int s, int kt) {
        uint32_t sa = sbase + s * STAGE_B;
        uint32_t sb = sa + A_STAGE_B;
        #pragma unroll
        for (int i = 0; i < 6; ++i) {               // 1536 16B chunks / 256 thr
            int c = tid + i * 256;
            uint32_t dst; const __half* g; int row, col;
            if (c < 512) { row = c >> 2; col = c & 3; dst = sa;
                           g = Abase + (size_t)row * DIM + kt * 32 + col * 8; }
            else { int cb = c - 512; row = cb >> 2; col = cb & 3; dst = sb;
                   g = Bbase + (size_t)row * DIM + kt * 32 + col * 8; }
            cp16(dst + (uint32_t)(row * (LDSK * 2) + col * 16), g);
        }
    };

    uint32_t acc[4][8][2];               // f16x2 accumulators
    #pragma unroll
    for (int i = 0; i < 4; i++)
        #pragma unroll
        for (int j = 0; j < 8; j++) { acc[i][j][0] = 0u; acc[i][j][1] = 0u; }

    // A: 4x ldmatrix.x4 per ks (64 rows x 16k). B: 4x ldmatrix.x4 (64 rows x 16k).
    int aRow = wm * 64 + (lane & 15);
    int aK0  = (lane >> 4) * 8;
    int bRow = wn * 64 + (lane & 7) + ((lane & 16) >> 1);
    int bK0  = ((lane >> 3) & 1) * 8;

    #pragma unroll
    for (int s = 0; s < STAGES - 1; ++s) { load_stage(s, s); cp_commit(); }

    for (int kt = 0; kt < KTILES; ++kt) {
        cp_wait<STAGES - 2>();
        __syncthreads();
        if (kt + STAGES - 1 < KTILES) load_stage((kt + STAGES - 1) % STAGES, kt + STAGES - 1);
        cp_commit();

        uint32_t sa = sbase + (kt % STAGES) * STAGE_B;
        uint32_t sb = sa + A_STAGE_B;
        #pragma unroll
        for (int ks = 0; ks < 2; ++ks) {
            uint32_t fa[4][4];
            #pragma unroll
            for (int mi = 0; mi < 4; mi++) {
                uint32_t addr = sa + (uint32_t)((aRow + mi * 16) * (LDSK * 2)
                                                + (ks * 16 + aK0) * 2);
                asm volatile("ldmatrix.sync.aligned.m8n8.x4.shared.b16 {%0,%1,%2,%3}, [%4];\n"
                    : "=r"(fa[mi][0]), "=r"(fa[mi][1]),
                      "=r"(fa[mi][2]), "=r"(fa[mi][3]) : "r"(addr));
            }
            uint32_t fb[4][4];
            #pragma unroll
            for (int np = 0; np < 4; np++) {
                uint32_t addr = sb + (uint32_t)((bRow + np * 16) * (LDSK * 2)
                                                + (ks * 16 + bK0) * 2);
                asm volatile("ldmatrix.sync.aligned.m8n8.x4.shared.b16 {%0,%1,%2,%3}, [%4];\n"
                    : "=r"(fb[np][0]), "=r"(fb[np][1]),
                      "=r"(fb[np][2]), "=r"(fb[np][3]) : "r"(addr));
            }
            #pragma unroll
            for (int mi = 0; mi < 4; mi++)
                #pragma unroll
                for (int ni = 0; ni < 8; ni++) {
                    uint32_t b0 = fb[ni >> 1][(ni & 1) * 2 + 0];
                    uint32_t b1 = fb[ni >> 1][(ni & 1) * 2 + 1];
                    asm volatile(
                        "mma.sync.aligned.m16n8k16.row.col.f16.f16.f16.f16 "
                        "{%0,%1}, {%2,%3,%4,%5}, {%6,%7}, {%0,%1};\n"
                        : "+r"(acc[mi][ni][0]), "+r"(acc[mi][ni][1])
                        : "r"(fa[mi][0]), "r"(fa[mi][1]),
                          "r"(fa[mi][2]), "r"(fa[mi][3]),
                          "r"(b0), "r"(b1));
                }
        }
    }

    // Epilogue: accumulators are already packed fp16 pairs -> direct store
    #pragma unroll
    for (int mi = 0; mi < 4; mi++) {
        #pragma unroll
        for (int ni = 0; ni < 8; ni++) {
            int row = bm * 128 + wm * 64 + mi * 16 + (lane >> 2);
            int col = bn * 256 + wn * 64 + ni * 8 + (lane & 3) * 2;
            *(uint32_t*)&g_neg[(size_t)row * QSIZE + col]       = acc[mi][ni][0];
            *(uint32_t*)&g_neg[(size_t)(row + 8) * QSIZE + col] = acc[mi][ni][1];
        }
    }
}

// ---------------------------------------------------------------------------
// k_select: pass1 (load+max+hist), fused pass2 (f16x2 exp + exp-table), gather.
// All exp sums in scaled domain e^((s-rowmax)/T).
// ---------------------------------------------------------------------------
#define SEL_T 512
#define CBUF_CAP 8192
#define SEL_SMEM (QSIZE*2 + 2048*4 + CBUF_CAP*2)

__device__ __forceinline__ uint32_t h2ex2(uint32_t x) {
    uint32_t r;
    asm("ex2.approx.f16x2 %0, %1;" : "=r"(r) : "r"(x));
    return r;
}

__device__ __forceinline__ void find_bin(int* hist, int target, int* scs,
                                         int* out_bin, int* out_above, int tid) {
    int base = tid * 4;
    int c = hist[base] + hist[base+1] + hist[base+2] + hist[base+3];
    scs[tid] = c;
    __syncthreads();
    #pragma unroll
    for (int d = 1; d < SEL_T; d <<= 1) {
        int v = (tid + d < SEL_T) ? scs[tid + d] : 0;
        __syncthreads();
        scs[tid] += v;
        __syncthreads();
    }
    int Sincl = scs[tid];
    int Sexcl = (tid + 1 < SEL_T) ? scs[tid + 1] : 0;
    if (Sexcl < target && Sincl >= target) {
        int ca = Sexcl;
        #pragma unroll
        for (int j = 3; j >= 0; --j) {
            int h = hist[base + j];
            if (ca + h >= target) { *out_bin = base + j; *out_above = ca; break; }
            ca += h;
        }
    }
}

__global__ __launch_bounds__(SEL_T) void k_select(const int* __restrict__ ridx) {
    extern __shared__ unsigned char dyn2[];
    __half*  srow  = (__half*)dyn2;                         // 65536 B
    __half2* srow2 = (__half2*)dyn2;
    int*     hist  = (int*)(dyn2 + QSIZE*2);                // 8192 B
    __half*  cbuf  = (__half*)(dyn2 + QSIZE*2 + 2048*4);    // 16384 B
    __shared__ int   scs[SEL_T];
    __shared__ float wred[SEL_T/32];
    __shared__ int   s_bin, s_above, s_nc;
    __shared__ float s_max;

    int b = blockIdx.x, tid = threadIdx.x;

    for (int i = tid; i < 2048; i += SEL_T) hist[i] = 0;
    if (tid == 0) s_nc = 0;
    __syncthreads();

    // ---- pass 1: load row, rowmax (f16 pairwise), level-1 histogram
    const uint4* src = (const uint4*)(g_neg + (size_t)b * QSIZE);
    uint4* drow = (uint4*)srow;
    __half2 hm = __floats2half2_rn(-2.0f, -2.0f);
    for (int i = tid; i < QSIZE / 8; i += SEL_T) {
        uint4 v = src[i]; drow[i] = v;
        uint32_t ws[4] = {v.x, v.y, v.z, v.w};
        #pragma unroll
        for (int q = 0; q < 4; ++q) {
            __half2 h2 = *(__half2*)&ws[q];
            hm = __hmax2(hm, h2);
            float2 f = __half22float2(h2);
            int b0 = (int)((f.x + 1.0f) * 1024.0f); b0 = min(max(b0, 0), 2047);
            int b1 = (int)((f.y + 1.0f) * 1024.0f); b1 = min(max(b1, 0), 2047);
            atomicAdd(&hist[b0], 1);
            atomicAdd(&hist[b1], 1);
        }
    }
    float lmax = fmaxf(__low2float(hm), __high2float(hm));
    #pragma unroll
    for (int o = 16; o; o >>= 1) lmax = fmaxf(lmax, __shfl_xor_sync(0xFFFFFFFFu, lmax, o));
    if ((tid & 31) == 0) wred[tid >> 5] = lmax;
    __syncthreads();
    if (tid == 0) {
        float m = -2.0f;
        for (int w = 0; w < SEL_T/32; ++w) m = fmaxf(m, wred[w]);
        s_max = m;
    }
    __syncthreads();
    float rm = s_max;

    find_bin(hist, NHARD, scs, &s_bin, &s_above, tid);
    __syncthreads();
    int bin1 = s_bin, need = NHARD - s_above;
    float lo = (float)bin1 * (1.0f / 1024.0f) - 1.0f;
    __syncthreads();

    // ---- pass 2 (fused): masked scaled-exp sum, boundary compaction,
    //      overwrite srow with e^((s-rm)/T) as the gather table.
    float accx = 0.0f, accy = 0.0f;
    for (int i = tid; i < QSIZE / 2; i += SEL_T) {
        __half2 v2 = srow2[i];
        float2 f = __half22float2(v2);
        int b0 = (int)((f.x + 1.0f) * 1024.0f); b0 = min(max(b0, 0), 2047);
        int b1 = (int)((f.y + 1.0f) * 1024.0f); b1 = min(max(b1, 0), 2047);
        if (b0 == bin1) { int p = atomicAdd(&s_nc, 1); if (p < CBUF_CAP) cbuf[p] = __low2half(v2); }
        if (b1 == bin1) { int p = atomicAdd(&s_nc, 1); if (p < CBUF_CAP) cbuf[p] = __high2half(v2); }
        __half2 xh = __floats2half2_rn((f.x - rm) * KEXP, (f.y - rm) * KEXP);
        uint32_t eu = h2ex2(*(uint32_t*)&xh);
        __half2 e2 = *(__half2*)&eu;
        float2 ef = __half22float2(e2);
        if (b0 > bin1) accx += ef.x;
        if (b1 > bin1) accy += ef.y;
        srow2[i] = e2;
    }
    float acc = accx + accy;
    __syncthreads();

    // ---- level 2 on the compacted boundary bin
    int nc = min(s_nc, CBUF_CAP);
    for (int i = tid; i < 2048; i += SEL_T) hist[i] = 0;
    __syncthreads();
    for (int i = tid; i < nc; i += SEL_T) {
        float s = __half2float(cbuf[i]);
        int sb = (int)((s - lo) * (1024.0f * 2048.0f)); sb = min(max(sb, 0), 2047);
        atomicAdd(&hist[sb], 1);
    }
    __syncthreads();
    find_bin(hist, need, scs, &s_bin, &s_above, tid);
    __syncthreads();
    int sb1 = s_bin, above2 = s_above;
    for (int i = tid; i < nc; i += SEL_T) {
        float s = __half2float(cbuf[i]);
        int sb = (int)((s - lo) * (1024.0f * 2048.0f)); sb = min(max(sb, 0), 2047);
        if (sb > sb1) acc += __expf((s - rm) * INV_T);
    }
    if (tid == 0) {
        int rem = need - above2;
        float smid = lo + ((float)sb1 + 0.5f) * (1.0f / (1024.0f * 2048.0f));
        acc += (float)rem * __expf((smid - rm) * INV_T);
    }

    // ---- random-negative gather: pure table lookup (no MUFU)
    const int2* ri2 = (const int2*)(ridx + (size_t)b * NRAND);
    for (int i = tid; i < NRAND / 2; i += SEL_T) {
        int2 p = __ldg(ri2 + i);
        acc += __half2float(srow[p.x]) + __half2float(srow[p.y]);
    }

    #pragma unroll
    for (int o = 16; o; o >>= 1) acc += __shfl_xor_sync(0xFFFFFFFFu, acc, o);
    if ((tid & 31) == 0) wred[tid >> 5] = acc;
    __syncthreads();
    if (tid == 0) {
        float tot = 0.0f;
        for (int w = 0; w < SEL_T/32; ++w) tot += wred[w];
        float p_sh = (g_pos[b] - rm) * INV_T;
        tot += __expf(p_sh);
        atomicAdd(&g_sums[0], (double)(logf(tot) - p_sh));
        atomicAdd(&g_sums[1], (g_pos[b] >= rm) ? 1.0 : 0.0);
    }
}

__global__ void k_final(float* out, int n) {
    if (n >= 1) out[0] = (float)(g_sums[0] / (double)BATCH);
    if (n >= 2) out[1] = (float)(g_sums[1] / (double)BATCH);
}

// ---------------------------------------------------------------------------
extern "C" void kernel_launch(void* const* d_in, const int* in_sizes, int n_in,
                              void* d_out, int out_size) {
    const float* eeg   = (const float*)d_in[0];
    const float* clip  = (const float*)d_in[1];
    const float* queue = (const float*)d_in[2];
    const int*   ridx  = (const int*)d_in[3];
    float* out = (float*)d_out;

    cudaFuncSetAttribute(k_gemm,   cudaFuncAttributeMaxDynamicSharedMemorySize, GEMM_SMEM);
    cudaFuncSetAttribute(k_select, cudaFuncAttributeMaxDynamicSharedMemorySize, SEL_SMEM);

    k_zero<<<1, 1>>>();
    k_norm<<<BATCH, 128>>>(eeg, clip);
    k_convq<<<QSIZE * DIM / 4 / 256, 256>>>(queue);
    k_gemm<<<dim3(QSIZE / 256, BATCH / 128), 256, GEMM_SMEM>>>();
    k_select<<<BATCH, SEL_T, SEL_SMEM>>>(ridx);
    k_final<<<1, 1>>>(out, out_size);
}

// round 10
// speedup vs baseline: 1.4717x; 1.0113x over previous
#include <cuda_runtime.h>
#include <cuda_bf16.h>
#include <cuda_fp16.h>
#include <cstdint>
#include <cstddef>

// Problem constants
#define BATCH   4096
#define DIM     512
#define QSIZE   32768
#define NHARD   9830
#define NRAND   22938
#define INV_T   (1.0f/0.07f)
#define KEXP    (INV_T * 1.44269504f)   // log2(e)/T

// -------- device scratch (static allocation; no cudaMalloc allowed) --------
__device__ __half  g_eegn[BATCH * DIM];            // 4 MB  normalized eeg, fp16
__device__ __half  g_qbf[QSIZE * DIM];             // 32 MB queue, fp16
__device__ __half  g_neg[(size_t)BATCH * QSIZE];   // 256 MB
__device__ float   g_pos[BATCH];
__device__ double  g_sums[2];

// ---------------------------------------------------------------------------
__global__ void k_zero() { g_sums[0] = 0.0; g_sums[1] = 0.0; }

__global__ __launch_bounds__(128) void k_norm(const float* __restrict__ eeg,
                                              const float* __restrict__ clip) {
    int b = blockIdx.x, t = threadIdx.x;
    float4 e = ((const float4*)(eeg  + (size_t)b * DIM))[t];
    float4 c = ((const float4*)(clip + (size_t)b * DIM))[t];
    float se = e.x*e.x + e.y*e.y + e.z*e.z + e.w*e.w;
    float sc = c.x*c.x + c.y*c.y + c.z*c.z + c.w*c.w;
    float sd = e.x*c.x + e.y*c.y + e.z*c.z + e.w*c.w;
    #pragma unroll
    for (int o = 16; o; o >>= 1) {
        se += __shfl_down_sync(0xFFFFFFFFu, se, o);
        sc += __shfl_down_sync(0xFFFFFFFFu, sc, o);
        sd += __shfl_down_sync(0xFFFFFFFFu, sd, o);
    }
    __shared__ float rs[3][4];
    __shared__ float sInvE;
    int w = t >> 5, l = t & 31;
    if (l == 0) { rs[0][w] = se; rs[1][w] = sc; rs[2][w] = sd; }
    __syncthreads();
    if (t == 0) {
        float SE = rs[0][0] + rs[0][1] + rs[0][2] + rs[0][3];
        float SC = rs[1][0] + rs[1][1] + rs[1][2] + rs[1][3];
        float SD = rs[2][0] + rs[2][1] + rs[2][2] + rs[2][3];
        float ie = 1.0f / fmaxf(sqrtf(SE), 1e-12f);
        float ic = 1.0f / fmaxf(sqrtf(SC), 1e-12f);
        sInvE = ie;
        g_pos[b] = SD * ie * ic;
    }
    __syncthreads();
    float ie = sInvE;
    __half* dst = g_eegn + (size_t)b * DIM + t * 4;
    dst[0] = __float2half(e.x * ie);
    dst[1] = __float2half(e.y * ie);
    dst[2] = __float2half(e.z * ie);
    dst[3] = __float2half(e.w * ie);
}

__global__ __launch_bounds__(256) void k_convq(const float* __restrict__ q) {
    int i = blockIdx.x * 256 + threadIdx.x;
    float4 v = ((const float4*)q)[i];
    __half2* d = (__half2*)g_qbf;
    d[2 * i]     = __floats2half2_rn(v.x, v.y);
    d[2 * i + 1] = __floats2half2_rn(v.z, v.w);
}

// ---------------------------------------------------------------------------
// mma.sync fp16 GEMM, f16 accumulate. (UNCHANGED from round 9 — best config)
// CTA tile 128x256, 256 threads, warp grid 2x4, warp tile 64x64.
// 3-stage cp.async, 92KB smem -> 2 CTAs/SM.
// ---------------------------------------------------------------------------
__device__ __forceinline__ uint32_t smem_u32(const void* p) {
    return (uint32_t)__cvta_generic_to_shared(p);
}
__device__ __forceinline__ void cp16(uint32_t s, const void* g) {
    asm volatile("cp.async.cg.shared.global [%0], [%1], 16;\n" :: "r"(s), "l"(g));
}
__device__ __forceinline__ void cp_commit() { asm volatile("cp.async.commit_group;\n"); }
template <int N> __device__ __forceinline__ void cp_wait() {
    asm volatile("cp.async.wait_group %0;\n" :: "n"(N));
}

#define LDSK 40                        // 32 + 8 pad elems: 80B rows
#define STAGES 3
#define KTILES 16                      // DIM / 32
#define A_STAGE_B (128 * LDSK * 2)     // 10240 B
#define B_STAGE_B (256 * LDSK * 2)     // 20480 B
#define STAGE_B   (A_STAGE_B + B_STAGE_B)
#define GEMM_SMEM (STAGES * STAGE_B)   // 92160 B -> 2 CTAs/SM

__global__ __launch_bounds__(256, 2) void k_gemm() {
    extern __shared__ __align__(16) unsigned char smraw[];
    uint32_t sbase = smem_u32(smraw);
    int tid = threadIdx.x, warp = tid >> 5, lane = tid & 31;
    int bn = blockIdx.x, bm = blockIdx.y;
    int wm = warp & 1, wn = warp >> 1;   // 2(m) x 4(n); warp tile 64x64

    const __half* Abase = g_eegn + (size_t)bm * 128 * DIM;
    const __half* Bbase = g_qbf  + (size_t)bn * 256 * DIM;

    auto load_stage = [&](int s, int kt) {
        uint32_t sa = sbase + s * STAGE_B;
        uint32_t sb = sa + A_STAGE_B;
        #pragma unroll
        for (int i = 0; i < 6; ++i) {               // 1536 16B chunks / 256 thr
            int c = tid + i * 256;
            uint32_t dst; const __half* g; int row, col;
            if (c < 512) { row = c >> 2; col = c & 3; dst = sa;
                           g = Abase + (size_t)row * DIM + kt * 32 + col * 8; }
            else { int cb = c - 512; row = cb >> 2; col = cb & 3; dst = sb;
                   g = Bbase + (size_t)row * DIM + kt * 32 + col * 8; }
            cp16(dst + (uint32_t)(row * (LDSK * 2) + col * 16), g);
        }
    };

    uint32_t acc[4][8][2];               // f16x2 accumulators
    #pragma unroll
    for (int i = 0; i < 4; i++)
        #pragma unroll
        for (int j = 0; j < 8; j++) { acc[i][j][0] = 0u; acc[i][j][1] = 0u; }

    int aRow = wm * 64 + (lane & 15);
    int aK0  = (lane >> 4) * 8;
    int bRow = wn * 64 + (lane & 7) + ((lane & 16) >> 1);
    int bK0  = ((lane >> 3) & 1) * 8;

    #pragma unroll
    for (int s = 0; s < STAGES - 1; ++s) { load_stage(s, s); cp_commit(); }

    for (int kt = 0; kt < KTILES; ++kt) {
        cp_wait<STAGES - 2>();
        __syncthreads();
        if (kt + STAGES - 1 < KTILES) load_stage((kt + STAGES - 1) % STAGES, kt + STAGES - 1);
        cp_commit();

        uint32_t sa = sbase + (kt % STAGES) * STAGE_B;
        uint32_t sb = sa + A_STAGE_B;
        #pragma unroll
        for (int ks = 0; ks < 2; ++ks) {
            uint32_t fa[4][4];
            #pragma unroll
            for (int mi = 0; mi < 4; mi++) {
                uint32_t addr = sa + (uint32_t)((aRow + mi * 16) * (LDSK * 2)
                                                + (ks * 16 + aK0) * 2);
                asm volatile("ldmatrix.sync.aligned.m8n8.x4.shared.b16 {%0,%1,%2,%3}, [%4];\n"
                    : "=r"(fa[mi][0]), "=r"(fa[mi][1]),
                      "=r"(fa[mi][2]), "=r"(fa[mi][3]) : "r"(addr));
            }
            uint32_t fb[4][4];
            #pragma unroll
            for (int np = 0; np < 4; np++) {
                uint32_t addr = sb + (uint32_t)((bRow + np * 16) * (LDSK * 2)
                                                + (ks * 16 + bK0) * 2);
                asm volatile("ldmatrix.sync.aligned.m8n8.x4.shared.b16 {%0,%1,%2,%3}, [%4];\n"
                    : "=r"(fb[np][0]), "=r"(fb[np][1]),
                      "=r"(fb[np][2]), "=r"(fb[np][3]) : "r"(addr));
            }
            #pragma unroll
            for (int mi = 0; mi < 4; mi++)
                #pragma unroll
                for (int ni = 0; ni < 8; ni++) {
                    uint32_t b0 = fb[ni >> 1][(ni & 1) * 2 + 0];
                    uint32_t b1 = fb[ni >> 1][(ni & 1) * 2 + 1];
                    asm volatile(
                        "mma.sync.aligned.m16n8k16.row.col.f16.f16.f16.f16 "
                        "{%0,%1}, {%2,%3,%4,%5}, {%6,%7}, {%0,%1};\n"
                        : "+r"(acc[mi][ni][0]), "+r"(acc[mi][ni][1])
                        : "r"(fa[mi][0]), "r"(fa[mi][1]),
                          "r"(fa[mi][2]), "r"(fa[mi][3]),
                          "r"(b0), "r"(b1));
                }
        }
    }

    #pragma unroll
    for (int mi = 0; mi < 4; mi++) {
        #pragma unroll
        for (int ni = 0; ni < 8; ni++) {
            int row = bm * 128 + wm * 64 + mi * 16 + (lane >> 2);
            int col = bn * 256 + wn * 64 + ni * 8 + (lane & 3) * 2;
            *(uint32_t*)&g_neg[(size_t)row * QSIZE + col]       = acc[mi][ni][0];
            *(uint32_t*)&g_neg[(size_t)(row + 8) * QSIZE + col] = acc[mi][ni][1];
        }
    }
}

// ---------------------------------------------------------------------------
// k_select: 1024-bin histogram (level-1) + 1024 sub-bins (level-2).
// Smem trimmed to ~72KB dynamic -> 3 CTAs/SM (waves 13.8 -> 9.2).
// ---------------------------------------------------------------------------
#define SEL_T 512
#define NBIN 1024
#define CBUF_CAP 1024
#define SEL_SMEM (QSIZE*2 + NBIN*4 + CBUF_CAP*2)   // 65536+4096+2048 = 71680 B

__device__ __forceinline__ uint32_t h2ex2(uint32_t x) {
    uint32_t r;
    asm("ex2.approx.f16x2 %0, %1;" : "=r"(r) : "r"(x));
    return r;
}

// hist has NBIN bins; each thread owns NBIN/SEL_T = 2 bins.
__device__ __forceinline__ void find_bin(int* hist, int target, int* scs,
                                         int* out_bin, int* out_above, int tid) {
    int base = tid * 2;
    int c = hist[base] + hist[base + 1];
    scs[tid] = c;
    __syncthreads();
    #pragma unroll
    for (int d = 1; d < SEL_T; d <<= 1) {
        int v = (tid + d < SEL_T) ? scs[tid + d] : 0;
        __syncthreads();
        scs[tid] += v;
        __syncthreads();
    }
    int Sincl = scs[tid];
    int Sexcl = (tid + 1 < SEL_T) ? scs[tid + 1] : 0;
    if (Sexcl < target && Sincl >= target) {
        int ca = Sexcl;
        #pragma unroll
        for (int j = 1; j >= 0; --j) {
            int h = hist[base + j];
            if (ca + h >= target) { *out_bin = base + j; *out_above = ca; break; }
            ca += h;
        }
    }
}

__global__ __launch_bounds__(SEL_T, 3) void k_select(const int* __restrict__ ridx) {
    extern __shared__ unsigned char dyn2[];
    __half*  srow  = (__half*)dyn2;                          // 65536 B
    __half2* srow2 = (__half2*)dyn2;
    int*     hist  = (int*)(dyn2 + QSIZE*2);                 // 4096 B
    __half*  cbuf  = (__half*)(dyn2 + QSIZE*2 + NBIN*4);     // 2048 B
    __shared__ int   scs[SEL_T];
    __shared__ float wred[SEL_T/32];
    __shared__ int   s_bin, s_above, s_nc;
    __shared__ float s_max;

    int b = blockIdx.x, tid = threadIdx.x;

    for (int i = tid; i < NBIN; i += SEL_T) hist[i] = 0;
    if (tid == 0) s_nc = 0;
    __syncthreads();

    // ---- pass 1: load row, rowmax (f16 pairwise), level-1 histogram (1024 bins)
    const uint4* src = (const uint4*)(g_neg + (size_t)b * QSIZE);
    uint4* drow = (uint4*)srow;
    __half2 hm = __floats2half2_rn(-2.0f, -2.0f);
    for (int i = tid; i < QSIZE / 8; i += SEL_T) {
        uint4 v = src[i]; drow[i] = v;
        uint32_t ws[4] = {v.x, v.y, v.z, v.w};
        #pragma unroll
        for (int q = 0; q < 4; ++q) {
            __half2 h2 = *(__half2*)&ws[q];
            hm = __hmax2(hm, h2);
            float2 f = __half22float2(h2);
            int b0 = (int)((f.x + 1.0f) * 512.0f); b0 = min(max(b0, 0), NBIN - 1);
            int b1 = (int)((f.y + 1.0f) * 512.0f); b1 = min(max(b1, 0), NBIN - 1);
            atomicAdd(&hist[b0], 1);
            atomicAdd(&hist[b1], 1);
        }
    }
    float lmax = fmaxf(__low2float(hm), __high2float(hm));
    #pragma unroll
    for (int o = 16; o; o >>= 1) lmax = fmaxf(lmax, __shfl_xor_sync(0xFFFFFFFFu, lmax, o));
    if ((tid & 31) == 0) wred[tid >> 5] = lmax;
    __syncthreads();
    if (tid == 0) {
        float m = -2.0f;
        for (int w = 0; w < SEL_T/32; ++w) m = fmaxf(m, wred[w]);
        s_max = m;
    }
    __syncthreads();
    float rm = s_max;

    find_bin(hist, NHARD, scs, &s_bin, &s_above, tid);
    __syncthreads();
    int bin1 = s_bin, need = NHARD - s_above;
    float lo = (float)bin1 * (1.0f / 512.0f) - 1.0f;
    __syncthreads();

    // ---- pass 2 (fused): masked scaled-exp sum, boundary compaction,
    //      overwrite srow with e^((s-rm)/T) as the gather table.
    float accx = 0.0f, accy = 0.0f;
    for (int i = tid; i < QSIZE / 2; i += SEL_T) {
        __half2 v2 = srow2[i];
        float2 f = __half22float2(v2);
        int b0 = (int)((f.x + 1.0f) * 512.0f); b0 = min(max(b0, 0), NBIN - 1);
        int b1 = (int)((f.y + 1.0f) * 512.0f); b1 = min(max(b1, 0), NBIN - 1);
        if (b0 == bin1) { int p = atomicAdd(&s_nc, 1); if (p < CBUF_CAP) cbuf[p] = __low2half(v2); }
        if (b1 == bin1) { int p = atomicAdd(&s_nc, 1); if (p < CBUF_CAP) cbuf[p] = __high2half(v2); }
        __half2 xh = __floats2half2_rn((f.x - rm) * KEXP, (f.y - rm) * KEXP);
        uint32_t eu = h2ex2(*(uint32_t*)&xh);
        __half2 e2 = *(__half2*)&eu;
        float2 ef = __half22float2(e2);
        if (b0 > bin1) accx += ef.x;
        if (b1 > bin1) accy += ef.y;
        srow2[i] = e2;
    }
    float acc = accx + accy;
    __syncthreads();

    // ---- level 2 on the compacted boundary bin (1024 sub-bins, < fp16 ULP wide)
    int nc = min(s_nc, CBUF_CAP);
    for (int i = tid; i < NBIN; i += SEL_T) hist[i] = 0;
    __syncthreads();
    for (int i = tid; i < nc; i += SEL_T) {
        float s = __half2float(cbuf[i]);
        int sb = (int)((s - lo) * (512.0f * 1024.0f)); sb = min(max(sb, 0), NBIN - 1);
        atomicAdd(&hist[sb], 1);
    }
    __syncthreads();
    find_bin(hist, need, scs, &s_bin, &s_above, tid);
    __syncthreads();
    int sb1 = s_bin, above2 = s_above;
    for (int i = tid; i < nc; i += SEL_T) {
        float s = __half2float(cbuf[i]);
        int sb = (int)((s - lo) * (512.0f * 1024.0f)); sb = min(max(sb, 0), NBIN - 1);
        if (sb > sb1) acc += __expf((s - rm) * INV_T);
    }
    if (tid == 0) {
        int rem = need - above2;
        float smid = lo + ((float)sb1 + 0.5f) * (1.0f / (512.0f * 1024.0f));
        acc += (float)rem * __expf((smid - rm) * INV_T);
    }

    // ---- random-negative gather: pure table lookup (no MUFU)
    const int2* ri2 = (const int2*)(ridx + (size_t)b * NRAND);
    for (int i = tid; i < NRAND / 2; i += SEL_T) {
        int2 p = __ldg(ri2 + i);
        acc += __half2float(srow[p.x]) + __half2float(srow[p.y]);
    }

    #pragma unroll
    for (int o = 16; o; o >>= 1) acc += __shfl_xor_sync(0xFFFFFFFFu, acc, o);
    if ((tid & 31) == 0) wred[tid >> 5] = acc;
    __syncthreads();
    if (tid == 0) {
        float tot = 0.0f;
        for (int w = 0; w < SEL_T/32; ++w) tot += wred[w];
        float p_sh = (g_pos[b] - rm) * INV_T;
        tot += __expf(p_sh);
        atomicAdd(&g_sums[0], (double)(logf(tot) - p_sh));
        atomicAdd(&g_sums[1], (g_pos[b] >= rm) ? 1.0 : 0.0);
    }
}

__global__ void k_final(float* out, int n) {
    if (n >= 1) out[0] = (float)(g_sums[0] / (double)BATCH);
    if (n >= 2) out[1] = (float)(g_sums[1] / (double)BATCH);
}

// ---------------------------------------------------------------------------
extern "C" void kernel_launch(void* const* d_in, const int* in_sizes, int n_in,
                              void* d_out, int out_size) {
    const float* eeg   = (const float*)d_in[0];
    const float* clip  = (const float*)d_in[1];
    const float* queue = (const float*)d_in[2];
    const int*   ridx  = (const int*)d_in[3];
    float* out = (float*)d_out;

    cudaFuncSetAttribute(k_gemm,   cudaFuncAttributeMaxDynamicSharedMemorySize, GEMM_SMEM);
    cudaFuncSetAttribute(k_select, cudaFuncAttributeMaxDynamicSharedMemorySize, SEL_SMEM);

    k_zero<<<1, 1>>>();
    k_norm<<<BATCH, 128>>>(eeg, clip);
    k_convq<<<QSIZE * DIM / 4 / 256, 256>>>(queue);
    k_gemm<<<dim3(QSIZE / 256, BATCH / 128), 256, GEMM_SMEM>>>();
    k_select<<<BATCH, SEL_T, SEL_SMEM>>>(ridx);
    k_final<<<1, 1>>>(out, out_size);
}